// round 11
// baseline (speedup 1.0000x reference)
#include <cuda_runtime.h>
#include <cuda_fp16.h>
#include <cstdint>
#include <cstddef>

#define B_  32
#define L_  512
#define E_  768
#define F_  512
#define M_  (B_ * L_)
#define EPSF 1e-7f

#define OFF_APRED 0L
#define OFF_OPRED 49152L
#define OFF_SPRED 98304L
#define OFF_AINT  147456L
#define OFF_OINT  16924672L
#define OFF_CINT  33701888L
#define OFF_CCONV 46284800L

// fp16 operand pools
__device__ __half g_ah  [(size_t)M_ * E_];
__device__ __half g_oh  [(size_t)M_ * E_];
__device__ __half g_ch  [(size_t)M_ * E_];
__device__ __half g_cqh [(size_t)M_ * E_];
__device__ __half g_posh[(size_t)B_ * L_ * L_];
__device__ __half g_Wah [2304 * 512];
__device__ __half g_Woh [2304 * 512];
__device__ __half g_Wch [2304 * 768];
__device__ __half g_aconvh[(size_t)M_ * F_];
__device__ __half g_oconvh[(size_t)M_ * F_];
__device__ __half g_cconvh[(size_t)M_ * E_];
__device__ __half g_A1h[(size_t)B_ * L_ * L_];
__device__ __half g_A2h[(size_t)B_ * L_ * L_];
__device__ __half g_Gh [(size_t)B_ * L_ * L_];
__device__ __half g_WAh[(size_t)B_ * L_ * L_];
// fp32 scratch
__device__ float g_G [(size_t)B_ * L_ * L_];
__device__ float g_WA[(size_t)B_ * L_ * L_];
__device__ float g_inva[M_], g_invo[M_], g_invc[M_];
__device__ float g_rowsum[M_], g_colsum[M_], g_colsumP[M_];
__device__ float g_msum[B_];
__device__ float g_conf[M_];
__device__ float g_q[(size_t)B_ * E_];

// ---------------- helpers ----------------
__device__ __forceinline__ uint32_t su32(const void* p) {
    uint32_t a;
    asm("{ .reg .u64 t; cvta.to.shared.u64 t, %1; cvt.u32.u64 %0, t; }" : "=r"(a) : "l"(p));
    return a;
}
__device__ __forceinline__ void ldm_x4(uint32_t* r, uint32_t addr) {
    asm volatile("ldmatrix.sync.aligned.m8n8.x4.shared.b16 {%0,%1,%2,%3}, [%4];"
                 : "=r"(r[0]), "=r"(r[1]), "=r"(r[2]), "=r"(r[3]) : "r"(addr));
}
__device__ __forceinline__ void ldm_x4t(uint32_t* r, uint32_t addr) {
    asm volatile("ldmatrix.sync.aligned.m8n8.x4.trans.shared.b16 {%0,%1,%2,%3}, [%4];"
                 : "=r"(r[0]), "=r"(r[1]), "=r"(r[2]), "=r"(r[3]) : "r"(addr));
}
__device__ __forceinline__ void mma_f16(float* c, const uint32_t* a, const uint32_t* b) {
    asm volatile(
        "mma.sync.aligned.m16n8k16.row.col.f32.f16.f16.f32 "
        "{%0,%1,%2,%3}, {%4,%5,%6,%7}, {%8,%9}, {%0,%1,%2,%3};"
        : "+f"(c[0]), "+f"(c[1]), "+f"(c[2]), "+f"(c[3])
        : "r"(a[0]), "r"(a[1]), "r"(a[2]), "r"(a[3]), "r"(b[0]), "r"(b[1]));
}
__device__ __forceinline__ uint32_t pkh(float x, float y) {
    __half2 t = __floats2half2_rn(x, y);
    return *reinterpret_cast<uint32_t*>(&t);
}

// ---------------- fp16 tensor-core GEMM ----------------
// 128x128 CTA tile, 4 warps, 64x64 warp tile, BK=32, one barrier/chunk.
#define AROWB 80
#define NROWB 272
#define S_B   10240
#define STAGE 20480
#define SMEM_DYN (2 * STAGE)

template<bool GATHER, bool BNN>
__global__ __launch_bounds__(128, 2)
void tc_gemm(const __half* __restrict__ A, long long ab,
             const __half* __restrict__ Bm, long long bb, int ldb, int K,
             float* __restrict__ C, long long cb, int ldc,
             const float* __restrict__ bias,
             const float* __restrict__ rs, const float* __restrict__ cs,
             const float* __restrict__ addp,
             const float* __restrict__ rowv, const float* __restrict__ colv,
             float* __restrict__ C2, int ldc2,
             __half* __restrict__ Ch, long long cbh, int ldch)
{
    extern __shared__ char smem[];
    const int tid = threadIdx.x;
    const int lane = tid & 31, wid = tid >> 5;
    const int wm = wid & 1, wn = wid >> 1;
    const int m0 = blockIdx.x * 128, n0 = blockIdx.y * 128, bz = blockIdx.z;
    const uint32_t sb0 = su32(smem);

    const __half* Ab = GATHER ? A : (A + (size_t)bz * ab);
    const __half* Bb = Bm + (size_t)bz * bb;

    float c[4][8][4];
#pragma unroll
    for (int i = 0; i < 4; i++)
#pragma unroll
        for (int j = 0; j < 8; j++)
#pragma unroll
            for (int k = 0; k < 4; k++) c[i][j][k] = 0.f;

    const int nch = K / 32;
    uint4 va[4], vb[4];

    auto ldg = [&](int kc) {
        const int k0 = kc * 32;
#pragma unroll
        for (int p = 0; p < 4; p++) {
            const int idx = tid + p * 128, row = idx >> 2, c16 = idx & 3;
            if (GATHER) {
                const int gm = m0 + row, b = gm >> 9, l = gm & 511;
                const int tap = kc / 24, e0 = (kc - tap * 24) * 32;
                const int src = l + tap - 1;
                va[p] = ((unsigned)src < 512u)
                    ? *reinterpret_cast<const uint4*>(A + ((size_t)(b * 512 + src)) * 768 + e0 + c16 * 8)
                    : make_uint4(0u, 0u, 0u, 0u);
            } else {
                va[p] = *reinterpret_cast<const uint4*>(Ab + (size_t)(m0 + row) * K + k0 + c16 * 8);
            }
        }
        if (BNN) {
#pragma unroll
            for (int p = 0; p < 4; p++) {
                const int idx = tid + p * 128, kr = idx >> 4, c16 = idx & 15;
                vb[p] = *reinterpret_cast<const uint4*>(Bb + (size_t)(k0 + kr) * ldb + n0 + c16 * 8);
            }
        } else {
#pragma unroll
            for (int p = 0; p < 4; p++) {
                const int idx = tid + p * 128, row = idx >> 2, c16 = idx & 3;
                vb[p] = *reinterpret_cast<const uint4*>(Bb + (size_t)(n0 + row) * ldb + k0 + c16 * 8);
            }
        }
    };
    auto sts = [&](int s) {
        char* sp = smem + s * STAGE;
#pragma unroll
        for (int p = 0; p < 4; p++) {
            const int idx = tid + p * 128, row = idx >> 2, c16 = idx & 3;
            *reinterpret_cast<uint4*>(sp + row * AROWB + c16 * 16) = va[p];
        }
        if (BNN) {
#pragma unroll
            for (int p = 0; p < 4; p++) {
                const int idx = tid + p * 128, kr = idx >> 4, c16 = idx & 15;
                *reinterpret_cast<uint4*>(sp + S_B + kr * NROWB + c16 * 16) = vb[p];
            }
        } else {
#pragma unroll
            for (int p = 0; p < 4; p++) {
                const int idx = tid + p * 128, row = idx >> 2, c16 = idx & 3;
                *reinterpret_cast<uint4*>(sp + S_B + row * AROWB + c16 * 16) = vb[p];
            }
        }
    };

    const uint32_t a_lrow = (lane & 15), a_lcol = (lane >> 4) * 8;
    const uint32_t nt_lrow = (lane & 7) + ((lane >> 4) << 3), nt_lcol = ((lane >> 3) & 1) * 8;
    const uint32_t nn_krow = (lane & 7) + (((lane >> 3) & 1) << 3), nn_ncol = (lane >> 4) * 8;

    auto compute = [&](int s) {
        const uint32_t base = sb0 + s * STAGE;
#pragma unroll
        for (int ks = 0; ks < 2; ks++) {
            const int kk = ks * 16;
            uint32_t af[4][4];
#pragma unroll
            for (int mf = 0; mf < 4; mf++)
                ldm_x4(af[mf], base + (wm * 64 + mf * 16 + a_lrow) * AROWB + (kk + a_lcol) * 2);
#pragma unroll
            for (int nf2 = 0; nf2 < 4; nf2++) {
                uint32_t bt[4];
                if (BNN)
                    ldm_x4t(bt, base + S_B + (kk + nn_krow) * NROWB + (wn * 64 + nf2 * 16 + nn_ncol) * 2);
                else
                    ldm_x4(bt, base + S_B + (wn * 64 + nf2 * 16 + nt_lrow) * AROWB + (kk + nt_lcol) * 2);
#pragma unroll
                for (int mf = 0; mf < 4; mf++) {
                    mma_f16(c[mf][nf2 * 2 + 0], af[mf], bt);
                    mma_f16(c[mf][nf2 * 2 + 1], af[mf], bt + 2);
                }
            }
        }
    };

    ldg(0);
    sts(0);
    ldg(1);
    __syncthreads();
    for (int i = 0; i < nch; i++) {
        if (i + 1 < nch) sts((i + 1) & 1);
        if (i + 2 < nch) ldg(i + 2);
        compute(i & 1);
        __syncthreads();
    }

    const int tm = lane >> 2, tn = (lane & 3) * 2;
#pragma unroll
    for (int mf = 0; mf < 4; mf++) {
#pragma unroll
        for (int nf = 0; nf < 8; nf++) {
#pragma unroll
            for (int half = 0; half < 2; half++) {
                const int m = m0 + wm * 64 + mf * 16 + tm + half * 8;
                const int nn = n0 + wn * 64 + nf * 8 + tn;
                float v0 = c[mf][nf][half * 2 + 0];
                float v1 = c[mf][nf][half * 2 + 1];
                if (rs) { const float r = rs[bz * 512 + m]; v0 *= r; v1 *= r; }
                if (cs) { v0 *= cs[bz * 512 + nn]; v1 *= cs[bz * 512 + nn + 1]; }
                if (bias) {
                    v0 = fmaxf(v0 + bias[nn], 0.f);
                    v1 = fmaxf(v1 + bias[nn + 1], 0.f);
                }
                if (C) {
                    const size_t rowoff = (size_t)bz * cb + (size_t)m * ldc + nn;
                    if (addp) { v0 += addp[rowoff]; v1 += addp[rowoff + 1]; }
                    if (rowv) {
                        const float rv = rowv[bz * 512 + m];
                        v0 += rv * colv[(size_t)bz * ldc + nn];
                        v1 += rv * colv[(size_t)bz * ldc + nn + 1];
                    }
                    C[rowoff] = v0; C[rowoff + 1] = v1;
                }
                if (C2) {
                    float* c2 = C2 + (size_t)m * ldc2 + nn;
                    c2[0] = v0; c2[1] = v1;
                }
                if (Ch) {
                    *reinterpret_cast<__half2*>(Ch + (size_t)bz * cbh + (size_t)m * ldch + nn) =
                        __floats2half2_rn(v0, v1);
                }
            }
        }
    }
}

// ---------------- fp32 -> fp16 convert ----------------
__global__ void cvt_k(const float4* __restrict__ src, uint2* __restrict__ dst, int n4)
{
    const int i = blockIdx.x * 256 + threadIdx.x;
    if (i < n4) {
        float4 v = src[i];
        dst[i] = make_uint2(pkh(v.x, v.y), pkh(v.z, v.w));
    }
}

// ---------------- elementwise / reductions ----------------
__global__ void rowinv_h(const __half* __restrict__ X, int D, float* __restrict__ inv)
{
    const int m = blockIdx.x, t = threadIdx.x;
    float s = 0.f;
    const __half2* xr = reinterpret_cast<const __half2*>(X + (size_t)m * D);
    for (int k = t; k < D / 2; k += 256) {
        float2 v = __half22float2(xr[k]);
        s = fmaf(v.x, v.x, fmaf(v.y, v.y, s));
    }
    __shared__ float red[256];
    red[t] = s; __syncthreads();
    for (int st = 128; st > 0; st >>= 1) { if (t < st) red[t] += red[t + st]; __syncthreads(); }
    if (t == 0) inv[m] = rsqrtf(fmaxf(red[0], 1e-12f));
}
__global__ void exp_rowsum_k(const float* __restrict__ mask)
{
    const int row = blockIdx.x, t = threadIdx.x;
    const int b = row >> 9;
    const size_t idx = (size_t)row * L_ + t;
    float e = expf(g_G[idx]);
    g_G[idx] = e;
    float v = e * mask[b * L_ + t];
    __shared__ float red[512];
    red[t] = v; __syncthreads();
    for (int st = 256; st > 0; st >>= 1) { if (t < st) red[t] += red[t + st]; __syncthreads(); }
    if (t == 0) g_rowsum[row] = red[0];
}
__global__ void colsum_k(const float* __restrict__ src, const float* __restrict__ wmask,
                         float* __restrict__ dst)
{
    const int b = blockIdx.x, c = blockIdx.y * 128 + threadIdx.x;
    const float* S = src + (size_t)b * L_ * L_;
    float acc = 0.f;
#pragma unroll 4
    for (int r = 0; r < L_; r++) {
        float w = wmask ? wmask[b * L_ + r] : 1.f;
        acc = fmaf(S[(size_t)r * L_ + c], w, acc);
    }
    dst[b * L_ + c] = acc;
}
__global__ void colsum_hk(const __half* __restrict__ src, float* __restrict__ dst)
{
    const int b = blockIdx.x, c = blockIdx.y * 128 + threadIdx.x;
    const __half* S = src + (size_t)b * L_ * L_;
    float acc = 0.f;
#pragma unroll 4
    for (int r = 0; r < L_; r++)
        acc += __half2float(S[(size_t)r * L_ + c]);
    dst[b * L_ + c] = acc;
}
__global__ void qprop_k(const __half* __restrict__ cconvh)
{
    const int b = blockIdx.x, e = blockIdx.y * 128 + threadIdx.x;
    float acc = 0.f;
#pragma unroll 4
    for (int r = 0; r < L_; r++)
        acc = fmaf(g_colsumP[b * L_ + r],
                   __half2float(cconvh[((size_t)(b * L_ + r)) * E_ + e]), acc);
    g_q[b * E_ + e] = acc * g_msum[b];
}
__global__ void a12_k(const float* __restrict__ mask)
{
    __shared__ float s[32][33];
    const int b = blockIdx.z;
    const int i0 = blockIdx.y * 32, j0 = blockIdx.x * 32;
    const int tx = threadIdx.x, ty = threadIdx.y;
    const float* Eb = g_G + (size_t)b * L_ * L_;
    const float* mk = mask + b * L_;
    s[ty][tx] = Eb[(size_t)(i0 + ty) * L_ + j0 + tx];
    __syncthreads();
    float a1 = s[ty][tx] * mk[j0 + tx] / (g_rowsum[b * L_ + i0 + ty] + EPSF) * mk[i0 + ty];
    g_A1h[(size_t)b * L_ * L_ + (size_t)(i0 + ty) * L_ + j0 + tx] = __float2half_rn(a1);
    float a2 = s[tx][ty] * mk[i0 + tx] / (g_colsum[b * L_ + j0 + ty] + EPSF) * mk[j0 + ty];
    g_A2h[(size_t)b * L_ * L_ + (size_t)(j0 + ty) * L_ + i0 + tx] = __float2half_rn(a2);
}
__global__ void pred3_k(const float* __restrict__ X, int D,
                        const float* __restrict__ Wd, const float* __restrict__ bd,
                        float* __restrict__ out, float* __restrict__ conf)
{
    const int m = blockIdx.x, t = threadIdx.x;
    const float* xr = X + (size_t)m * D;
    float a0 = 0.f, a1 = 0.f, a2 = 0.f;
    for (int k4 = t; k4 < D / 4; k4 += 128) {
        float4 x = *reinterpret_cast<const float4*>(xr + k4 * 4);
        float4 w0 = *reinterpret_cast<const float4*>(Wd + k4 * 12);
        float4 w1 = *reinterpret_cast<const float4*>(Wd + k4 * 12 + 4);
        float4 w2 = *reinterpret_cast<const float4*>(Wd + k4 * 12 + 8);
        a0 = fmaf(x.x, w0.x, a0); a1 = fmaf(x.x, w0.y, a1); a2 = fmaf(x.x, w0.z, a2);
        a0 = fmaf(x.y, w0.w, a0); a1 = fmaf(x.y, w1.x, a1); a2 = fmaf(x.y, w1.y, a2);
        a0 = fmaf(x.z, w1.z, a0); a1 = fmaf(x.z, w1.w, a1); a2 = fmaf(x.z, w2.x, a2);
        a0 = fmaf(x.w, w2.y, a0); a1 = fmaf(x.w, w2.z, a1); a2 = fmaf(x.w, w2.w, a2);
    }
#pragma unroll
    for (int o = 16; o > 0; o >>= 1) {
        a0 += __shfl_down_sync(0xffffffffu, a0, o);
        a1 += __shfl_down_sync(0xffffffffu, a1, o);
        a2 += __shfl_down_sync(0xffffffffu, a2, o);
    }
    __shared__ float sh[4][3];
    const int w = t >> 5, ln = t & 31;
    if (ln == 0) { sh[w][0] = a0; sh[w][1] = a1; sh[w][2] = a2; }
    __syncthreads();
    if (t == 0) {
        float p0 = sh[0][0] + sh[1][0] + sh[2][0] + sh[3][0] + bd[0];
        float p1 = sh[0][1] + sh[1][1] + sh[2][1] + sh[3][1] + bd[1];
        float p2 = sh[0][2] + sh[1][2] + sh[2][2] + sh[3][2] + bd[2];
        out[(size_t)m * 3 + 0] = p0;
        out[(size_t)m * 3 + 1] = p1;
        out[(size_t)m * 3 + 2] = p2;
        if (conf) {
            float mx = fmaxf(p0, fmaxf(p1, p2));
            float e0 = expf(p0 - mx), e1 = expf(p1 - mx), e2 = expf(p2 - mx);
            conf[m] = fmaxf(0.f, 1.f - 2.f * e0 / (e0 + e1 + e2));
        }
    }
}
__global__ void msum_k(const float* __restrict__ mask)
{
    const int b = blockIdx.x, t = threadIdx.x;
    __shared__ float red[512];
    red[t] = mask[b * L_ + t]; __syncthreads();
    for (int st = 256; st > 0; st >>= 1) { if (t < st) red[t] += red[t + st]; __syncthreads(); }
    if (t == 0) g_msum[b] = red[0];
}
__global__ void smax_combine_k(const float* __restrict__ mask)
{
    const int row = blockIdx.x, t = threadIdx.x;
    const int b = row >> 9, i = row & 511;
    const size_t base = (size_t)row * L_;
    float v = g_WA[base + t];
    __shared__ float red[512];
    red[t] = v; __syncthreads();
    for (int st = 256; st > 0; st >>= 1) { if (t < st) red[t] = fmaxf(red[t], red[t + st]); __syncthreads(); }
    const float mx = red[0]; __syncthreads();
    float e = expf(v - mx) * mask[b * L_ + t];
    red[t] = e; __syncthreads();
    for (int st = 256; st > 0; st >>= 1) { if (t < st) red[t] += red[t + st]; __syncthreads(); }
    const float sum = red[0];
    float att = e / (sum + EPSF) * mask[b * L_ + i];
    g_WAh[base + t] = __float2half_rn(att + __half2float(g_A1h[base + t]));
}

// =====================================================================
extern "C" void kernel_launch(void* const* d_in, const int* in_sizes, int n_in,
                              void* d_out, int out_size)
{
    const float* aspect_in  = (const float*)d_in[0];
    const float* opinion_in = (const float*)d_in[1];
    const float* context_in = (const float*)d_in[2];
    const float* cq   = (const float*)d_in[3];
    const float* mask = (const float*)d_in[4];
    const float* pos  = (const float*)d_in[5];
    const float* Wa = (const float*)d_in[6],  *ba = (const float*)d_in[7];
    const float* Wo = (const float*)d_in[8],  *bo = (const float*)d_in[9];
    const float* Wc = (const float*)d_in[10], *bc = (const float*)d_in[11];
    const float* Wda = (const float*)d_in[12], *bda = (const float*)d_in[13];
    const float* Wdo = (const float*)d_in[14], *bdo = (const float*)d_in[15];
    const float* Wds = (const float*)d_in[16], *bds = (const float*)d_in[17];
    float* out = (float*)d_out;

    __half *ah, *oh, *ch, *cqh, *posh, *Wah, *Woh, *Wch;
    __half *aconvh, *oconvh, *cconvh, *A1h, *A2h, *Gh, *WAh;
    float *G, *WA, *inva, *invo, *invc, *colsum, *colsumP, *conf, *q;
    cudaGetSymbolAddress((void**)&ah,     g_ah);
    cudaGetSymbolAddress((void**)&oh,     g_oh);
    cudaGetSymbolAddress((void**)&ch,     g_ch);
    cudaGetSymbolAddress((void**)&cqh,    g_cqh);
    cudaGetSymbolAddress((void**)&posh,   g_posh);
    cudaGetSymbolAddress((void**)&Wah,    g_Wah);
    cudaGetSymbolAddress((void**)&Woh,    g_Woh);
    cudaGetSymbolAddress((void**)&Wch,    g_Wch);
    cudaGetSymbolAddress((void**)&aconvh, g_aconvh);
    cudaGetSymbolAddress((void**)&oconvh, g_oconvh);
    cudaGetSymbolAddress((void**)&cconvh, g_cconvh);
    cudaGetSymbolAddress((void**)&A1h,    g_A1h);
    cudaGetSymbolAddress((void**)&A2h,    g_A2h);
    cudaGetSymbolAddress((void**)&Gh,     g_Gh);
    cudaGetSymbolAddress((void**)&WAh,    g_WAh);
    cudaGetSymbolAddress((void**)&G,      g_G);
    cudaGetSymbolAddress((void**)&WA,     g_WA);
    cudaGetSymbolAddress((void**)&inva,   g_inva);
    cudaGetSymbolAddress((void**)&invo,   g_invo);
    cudaGetSymbolAddress((void**)&invc,   g_invc);
    cudaGetSymbolAddress((void**)&colsum, g_colsum);
    cudaGetSymbolAddress((void**)&colsumP,g_colsumP);
    cudaGetSymbolAddress((void**)&conf,   g_conf);
    cudaGetSymbolAddress((void**)&q,      g_q);

    cudaFuncSetAttribute(tc_gemm<true, true>,   cudaFuncAttributeMaxDynamicSharedMemorySize, SMEM_DYN);
    cudaFuncSetAttribute(tc_gemm<false, true>,  cudaFuncAttributeMaxDynamicSharedMemorySize, SMEM_DYN);
    cudaFuncSetAttribute(tc_gemm<false, false>, cudaFuncAttributeMaxDynamicSharedMemorySize, SMEM_DYN);

    // streams/events (created once; capture-safe thereafter)
    static cudaStream_t s1 = nullptr, s2 = nullptr;
    static cudaEvent_t ev[10] = {};
    if (!s1) {
        cudaStreamCreateWithFlags(&s1, cudaStreamNonBlocking);
        cudaStreamCreateWithFlags(&s2, cudaStreamNonBlocking);
        for (int i = 0; i < 10; i++) cudaEventCreateWithFlags(&ev[i], cudaEventDisableTiming);
    }
    cudaEvent_t evRoot = ev[0], evF = ev[1], evPos = ev[2], ev1 = ev[3], ev2 = ev[4],
                evA12 = ev[5], evConf = ev[6], evE1 = ev[7];

    // ---- FORK: side streams enter capture via event from stream 0 ----
    cudaEventRecord(evRoot, 0);
    cudaStreamWaitEvent(s1, evRoot, 0);
    cudaStreamWaitEvent(s2, evRoot, 0);

    // ---- head: conversions. default = conv-gating inputs only ----
    const int nIN = M_ * E_ / 4, nPOS = B_ * L_ * L_ / 4;
    cvt_k<<<(nIN + 255) / 256, 256>>>((const float4*)aspect_in,  (uint2*)ah, nIN);
    cvt_k<<<(nIN + 255) / 256, 256>>>((const float4*)opinion_in, (uint2*)oh, nIN);
    cvt_k<<<(nIN + 255) / 256, 256>>>((const float4*)context_in, (uint2*)ch, nIN);
    cudaEventRecord(evF, 0);

    // s1: Wo, pos, cq conversions, then conv_o after evF
    cvt_k<<<(2304 * 512 / 4 + 255) / 256, 256, 0, s1>>>((const float4*)Wo, (uint2*)Woh, 2304 * 512 / 4);
    cvt_k<<<(nPOS + 255) / 256, 256, 0, s1>>>((const float4*)pos, (uint2*)posh, nPOS);
    cudaEventRecord(evPos, s1);
    cvt_k<<<(nIN + 255) / 256, 256, 0, s1>>>((const float4*)cq, (uint2*)cqh, nIN);
    cudaStreamWaitEvent(s1, evF, 0);
    tc_gemm<true, true><<<dim3(128, 4, 1), 128, SMEM_DYN, s1>>>(
        oh, 0, Woh, 0, 512, 2304, out + OFF_OINT, 0, 1024, bo,
        nullptr, nullptr, nullptr, nullptr, nullptr, nullptr, 0, oconvh, 0, 512);
    rowinv_h<<<M_, 256, 0, s1>>>(oconvh, 512, invo);
    cudaEventRecord(ev1, s1);

    // s2: Wc conversion, conv_c after evF
    cvt_k<<<(2304 * 768 / 4 + 255) / 256, 256, 0, s2>>>((const float4*)Wc, (uint2*)Wch, 2304 * 768 / 4);
    cudaStreamWaitEvent(s2, evF, 0);
    tc_gemm<true, true><<<dim3(128, 6, 1), 128, SMEM_DYN, s2>>>(
        ch, 0, Wch, 0, 768, 2304, out + OFF_CCONV, 0, 768, bc,
        nullptr, nullptr, nullptr, nullptr, nullptr, nullptr, 0, cconvh, 0, 768);
    rowinv_h<<<M_, 256, 0, s2>>>(cconvh, 768, invc);
    cudaEventRecord(ev2, s2);

    // default: Wa conversion + conv_a
    cvt_k<<<(2304 * 512 / 4 + 255) / 256, 256>>>((const float4*)Wa, (uint2*)Wah, 2304 * 512 / 4);
    tc_gemm<true, true><<<dim3(128, 4, 1), 128, SMEM_DYN>>>(
        ah, 0, Wah, 0, 512, 2304, out + OFF_AINT, 0, 1024, ba,
        nullptr, nullptr, nullptr, nullptr, nullptr, nullptr, 0, aconvh, 0, 512);
    rowinv_h<<<M_, 256>>>(aconvh, 512, inva);

    // ---- chain A (default): gram (needs oconv -> wait ev1) ----
    cudaStreamWaitEvent(0, ev1, 0);
    tc_gemm<false, false><<<dim3(4, 4, B_), 128, SMEM_DYN>>>(
        aconvh, 512LL * 512, oconvh, 512LL * 512, 512, 512, G, 512LL * 512, 512,
        nullptr, inva, invo, nullptr, nullptr, nullptr, nullptr, 0, nullptr, 0, 0);
    exp_rowsum_k<<<M_, 512>>>(mask);
    colsum_k<<<dim3(B_, 4), 128>>>(G, mask, colsum);
    a12_k<<<dim3(16, 16, B_), dim3(32, 32)>>>(mask);
    cudaEventRecord(evA12, 0);
    tc_gemm<false, true><<<dim3(4, 4, B_), 128, SMEM_DYN>>>(
        A1h, 512LL * 512, oconvh, 512LL * 512, 512, 512, out + OFF_AINT + 512, 512LL * 1024, 1024,
        nullptr, nullptr, nullptr, nullptr, nullptr, nullptr, nullptr, 0, nullptr, 0, 0);
    pred3_k<<<M_, 128>>>(out + OFF_AINT, 1024, Wda, bda, out + OFF_APRED, nullptr);

    // ---- chain B (s1): context-attention front (needs cconv -> wait ev2) ----
    cudaStreamWaitEvent(s1, ev2, 0);
    tc_gemm<false, false><<<dim3(4, 4, B_), 128, SMEM_DYN, s1>>>(
        cqh, 512LL * 768, cconvh, 512LL * 768, 768, 768, nullptr, 0, 512,
        nullptr, nullptr, invc, nullptr, nullptr, nullptr, nullptr, 0, Gh, 512LL * 512, 512);
    tc_gemm<false, true><<<dim3(4, 4, B_), 128, SMEM_DYN, s1>>>(
        Gh, 512LL * 512, posh, 512LL * 512, 512, 512, WA, 512LL * 512, 512,
        nullptr, nullptr, nullptr, nullptr, nullptr, nullptr, nullptr, 0, nullptr, 0, 0);
    cudaStreamWaitEvent(s1, evA12, 0);
    smax_combine_k<<<M_, 512, 0, s1>>>(mask);

    // ---- chain C (s2): propagation pieces + opinion interact/pred ----
    cudaStreamWaitEvent(s2, evPos, 0);
    colsum_hk<<<dim3(B_, 4), 128, 0, s2>>>(posh, colsumP);
    msum_k<<<B_, 512, 0, s2>>>(mask);
    qprop_k<<<dim3(B_, 6), 128, 0, s2>>>(cconvh);
    cudaStreamWaitEvent(s2, evA12, 0);
    tc_gemm<false, true><<<dim3(4, 4, B_), 128, SMEM_DYN, s2>>>(
        A2h, 512LL * 512, aconvh, 512LL * 512, 512, 512, out + OFF_OINT + 512, 512LL * 1024, 1024,
        nullptr, nullptr, nullptr, nullptr, nullptr, nullptr, nullptr, 0, nullptr, 0, 0);
    pred3_k<<<M_, 128, 0, s2>>>(out + OFF_OINT, 1024, Wdo, bdo, out + OFF_OPRED, conf);
    cudaEventRecord(evConf, s2);

    // ---- s1 tail: final context GEMM ----
    cudaStreamWaitEvent(s1, evConf, 0);
    tc_gemm<false, true><<<dim3(4, 6, B_), 128, SMEM_DYN, s1>>>(
        WAh, 512LL * 512, cconvh, 512LL * 768, 768, 512, out + OFF_CINT, 512LL * 768, 768,
        nullptr, nullptr, nullptr, cq, conf, q, nullptr, 0, nullptr, 0, 0);
    pred3_k<<<M_, 128, 0, s1>>>(out + OFF_CINT, 768, Wds, bds, out + OFF_SPRED, nullptr);
    cudaEventRecord(evE1, s1);

    // ---- join ----
    cudaStreamWaitEvent(0, evE1, 0);
    cudaStreamWaitEvent(0, evConf, 0);
}

// round 12
// speedup vs baseline: 1.0151x; 1.0151x over previous
#include <cuda_runtime.h>
#include <cuda_fp16.h>
#include <cstdint>
#include <cstddef>

#define B_  32
#define L_  512
#define E_  768
#define F_  512
#define M_  (B_ * L_)
#define EPSF 1e-7f

#define OFF_APRED 0L
#define OFF_OPRED 49152L
#define OFF_SPRED 98304L
#define OFF_AINT  147456L
#define OFF_OINT  16924672L
#define OFF_CINT  33701888L
#define OFF_CCONV 46284800L

// fp16 operand pools
__device__ __half g_ah  [(size_t)M_ * E_];
__device__ __half g_oh  [(size_t)M_ * E_];
__device__ __half g_ch  [(size_t)M_ * E_];
__device__ __half g_cqh [(size_t)M_ * E_];
__device__ __half g_posh[(size_t)B_ * L_ * L_];
__device__ __half g_Wah [2304 * 512];
__device__ __half g_Woh [2304 * 512];
__device__ __half g_Wch [2304 * 768];
__device__ __half g_aconvh[(size_t)M_ * F_];
__device__ __half g_oconvh[(size_t)M_ * F_];
__device__ __half g_cconvh[(size_t)M_ * E_];
__device__ __half g_A1h[(size_t)B_ * L_ * L_];
__device__ __half g_A2h[(size_t)B_ * L_ * L_];
__device__ __half g_Gh [(size_t)B_ * L_ * L_];
__device__ __half g_WAh[(size_t)B_ * L_ * L_];
// fp32 scratch
__device__ float g_G [(size_t)B_ * L_ * L_];   // holds expG after gram
__device__ float g_WA[(size_t)B_ * L_ * L_];
__device__ float g_inva[M_], g_invo[M_], g_invc[M_];
__device__ float g_rowsum[M_], g_colsum[M_], g_colsumP[M_];
__device__ float g_msum[B_];
__device__ float g_conf[M_];
__device__ float g_q[(size_t)B_ * E_];

// ---------------- helpers ----------------
__device__ __forceinline__ uint32_t su32(const void* p) {
    uint32_t a;
    asm("{ .reg .u64 t; cvta.to.shared.u64 t, %1; cvt.u32.u64 %0, t; }" : "=r"(a) : "l"(p));
    return a;
}
__device__ __forceinline__ void ldm_x4(uint32_t* r, uint32_t addr) {
    asm volatile("ldmatrix.sync.aligned.m8n8.x4.shared.b16 {%0,%1,%2,%3}, [%4];"
                 : "=r"(r[0]), "=r"(r[1]), "=r"(r[2]), "=r"(r[3]) : "r"(addr));
}
__device__ __forceinline__ void ldm_x4t(uint32_t* r, uint32_t addr) {
    asm volatile("ldmatrix.sync.aligned.m8n8.x4.trans.shared.b16 {%0,%1,%2,%3}, [%4];"
                 : "=r"(r[0]), "=r"(r[1]), "=r"(r[2]), "=r"(r[3]) : "r"(addr));
}
__device__ __forceinline__ void mma_f16(float* c, const uint32_t* a, const uint32_t* b) {
    asm volatile(
        "mma.sync.aligned.m16n8k16.row.col.f32.f16.f16.f32 "
        "{%0,%1,%2,%3}, {%4,%5,%6,%7}, {%8,%9}, {%0,%1,%2,%3};"
        : "+f"(c[0]), "+f"(c[1]), "+f"(c[2]), "+f"(c[3])
        : "r"(a[0]), "r"(a[1]), "r"(a[2]), "r"(a[3]), "r"(b[0]), "r"(b[1]));
}
__device__ __forceinline__ uint32_t pkh(float x, float y) {
    __half2 t = __floats2half2_rn(x, y);
    return *reinterpret_cast<uint32_t*>(&t);
}

// ---------------- fp16 tensor-core GEMM, BK=64, one barrier/chunk (R10 config) ----------------
#define AROWB 144
#define NROWB 272
#define S_B   18432
#define STAGE 36864
#define SMEM_DYN (2 * STAGE)

template<bool GATHER, bool BNN>
__global__ __launch_bounds__(256, 2)
void tc_gemm(const __half* __restrict__ A, long long ab,
             const __half* __restrict__ Bm, long long bb, int ldb, int K,
             float* __restrict__ C, long long cb, int ldc,
             const float* __restrict__ bias,
             const float* __restrict__ rs, const float* __restrict__ cs,
             const float* __restrict__ addp,
             const float* __restrict__ rowv, const float* __restrict__ colv,
             float* __restrict__ C2, int ldc2,
             __half* __restrict__ Ch, long long cbh, int ldch,
             int doexp)
{
    extern __shared__ char smem[];
    const int tid = threadIdx.x;
    const int lane = tid & 31, wid = tid >> 5;
    const int wm = wid & 3, wn = wid >> 2;
    const int m0 = blockIdx.x * 128, n0 = blockIdx.y * 128, bz = blockIdx.z;
    const uint32_t sb0 = su32(smem);

    const __half* Ab = GATHER ? A : (A + (size_t)bz * ab);
    const __half* Bb = Bm + (size_t)bz * bb;

    float c[2][8][4];
#pragma unroll
    for (int i = 0; i < 2; i++)
#pragma unroll
        for (int j = 0; j < 8; j++)
#pragma unroll
            for (int k = 0; k < 4; k++) c[i][j][k] = 0.f;

    const int nch = K / 64;
    uint4 va[4], vb[4];

    auto ldg = [&](int kc) {
        const int k0 = kc * 64;
#pragma unroll
        for (int p = 0; p < 4; p++) {
            const int idx = tid + p * 256, row = idx >> 3, c16 = idx & 7;
            if (GATHER) {
                const int gm = m0 + row, b = gm >> 9, l = gm & 511;
                const int tap = kc / 12, e0 = (kc - tap * 12) * 64;
                const int src = l + tap - 1;
                va[p] = ((unsigned)src < 512u)
                    ? *reinterpret_cast<const uint4*>(A + ((size_t)(b * 512 + src)) * 768 + e0 + c16 * 8)
                    : make_uint4(0u, 0u, 0u, 0u);
            } else {
                va[p] = *reinterpret_cast<const uint4*>(Ab + (size_t)(m0 + row) * K + k0 + c16 * 8);
            }
        }
        if (BNN) {
#pragma unroll
            for (int p = 0; p < 4; p++) {
                const int idx = tid + p * 256, kr = idx >> 4, c16 = idx & 15;
                vb[p] = *reinterpret_cast<const uint4*>(Bb + (size_t)(k0 + kr) * ldb + n0 + c16 * 8);
            }
        } else {
#pragma unroll
            for (int p = 0; p < 4; p++) {
                const int idx = tid + p * 256, row = idx >> 3, c16 = idx & 7;
                vb[p] = *reinterpret_cast<const uint4*>(Bb + (size_t)(n0 + row) * ldb + k0 + c16 * 8);
            }
        }
    };
    auto sts = [&](int s) {
        char* sp = smem + s * STAGE;
#pragma unroll
        for (int p = 0; p < 4; p++) {
            const int idx = tid + p * 256, row = idx >> 3, c16 = idx & 7;
            *reinterpret_cast<uint4*>(sp + row * AROWB + c16 * 16) = va[p];
        }
        if (BNN) {
#pragma unroll
            for (int p = 0; p < 4; p++) {
                const int idx = tid + p * 256, kr = idx >> 4, c16 = idx & 15;
                *reinterpret_cast<uint4*>(sp + S_B + kr * NROWB + c16 * 16) = vb[p];
            }
        } else {
#pragma unroll
            for (int p = 0; p < 4; p++) {
                const int idx = tid + p * 256, row = idx >> 3, c16 = idx & 7;
                *reinterpret_cast<uint4*>(sp + S_B + row * AROWB + c16 * 16) = vb[p];
            }
        }
    };

    const uint32_t a_lrow = (lane & 15), a_lcol = (lane >> 4) * 8;
    const uint32_t nt_lrow = (lane & 7) + ((lane >> 4) << 3), nt_lcol = ((lane >> 3) & 1) * 8;
    const uint32_t nn_krow = (lane & 7) + (((lane >> 3) & 1) << 3), nn_ncol = (lane >> 4) * 8;

    auto compute = [&](int s) {
        const uint32_t base = sb0 + s * STAGE;
#pragma unroll
        for (int ks = 0; ks < 4; ks++) {
            const int kk = ks * 16;
            uint32_t af[2][4];
#pragma unroll
            for (int mf = 0; mf < 2; mf++)
                ldm_x4(af[mf], base + (wm * 32 + mf * 16 + a_lrow) * AROWB + (kk + a_lcol) * 2);
#pragma unroll
            for (int nf2 = 0; nf2 < 4; nf2++) {
                uint32_t bt[4];
                if (BNN)
                    ldm_x4t(bt, base + S_B + (kk + nn_krow) * NROWB + (wn * 64 + nf2 * 16 + nn_ncol) * 2);
                else
                    ldm_x4(bt, base + S_B + (wn * 64 + nf2 * 16 + nt_lrow) * AROWB + (kk + nt_lcol) * 2);
#pragma unroll
                for (int mf = 0; mf < 2; mf++) {
                    mma_f16(c[mf][nf2 * 2 + 0], af[mf], bt);
                    mma_f16(c[mf][nf2 * 2 + 1], af[mf], bt + 2);
                }
            }
        }
    };

    ldg(0);
    sts(0);
    ldg(1);
    __syncthreads();
    for (int i = 0; i < nch; i++) {
        if (i + 1 < nch) sts((i + 1) & 1);
        if (i + 2 < nch) ldg(i + 2);
        compute(i & 1);
        __syncthreads();
    }

    const int tm = lane >> 2, tn = (lane & 3) * 2;
#pragma unroll
    for (int mf = 0; mf < 2; mf++) {
#pragma unroll
        for (int nf = 0; nf < 8; nf++) {
#pragma unroll
            for (int half = 0; half < 2; half++) {
                const int m = m0 + wm * 32 + mf * 16 + tm + half * 8;
                const int nn = n0 + wn * 64 + nf * 8 + tn;
                float v0 = c[mf][nf][half * 2 + 0];
                float v1 = c[mf][nf][half * 2 + 1];
                if (rs) { const float r = rs[bz * 512 + m]; v0 *= r; v1 *= r; }
                if (cs) { v0 *= cs[bz * 512 + nn]; v1 *= cs[bz * 512 + nn + 1]; }
                if (doexp) { v0 = expf(v0); v1 = expf(v1); }
                if (bias) {
                    v0 = fmaxf(v0 + bias[nn], 0.f);
                    v1 = fmaxf(v1 + bias[nn + 1], 0.f);
                }
                if (C) {
                    const size_t rowoff = (size_t)bz * cb + (size_t)m * ldc + nn;
                    if (addp) { v0 += addp[rowoff]; v1 += addp[rowoff + 1]; }
                    if (rowv) {
                        const float rv = rowv[bz * 512 + m];
                        v0 += rv * colv[(size_t)bz * ldc + nn];
                        v1 += rv * colv[(size_t)bz * ldc + nn + 1];
                    }
                    C[rowoff] = v0; C[rowoff + 1] = v1;
                }
                if (C2) {
                    float* c2 = C2 + (size_t)m * ldc2 + nn;
                    c2[0] = v0; c2[1] = v1;
                }
                if (Ch) {
                    *reinterpret_cast<__half2*>(Ch + (size_t)bz * cbh + (size_t)m * ldch + nn) =
                        __floats2half2_rn(v0, v1);
                }
            }
        }
    }
}

// ---------------- fp32 -> fp16 convert ----------------
__global__ void cvt_k(const float4* __restrict__ src, uint2* __restrict__ dst, int n4)
{
    const int i = blockIdx.x * 256 + threadIdx.x;
    if (i < n4) {
        float4 v = src[i];
        dst[i] = make_uint2(pkh(v.x, v.y), pkh(v.z, v.w));
    }
}

// ---------------- elementwise / reductions ----------------
__global__ void rowinv_h(const __half* __restrict__ X, int D, float* __restrict__ inv)
{
    const int m = blockIdx.x, t = threadIdx.x;
    float s = 0.f;
    const __half2* xr = reinterpret_cast<const __half2*>(X + (size_t)m * D);
    for (int k = t; k < D / 2; k += 256) {
        float2 v = __half22float2(xr[k]);
        s = fmaf(v.x, v.x, fmaf(v.y, v.y, s));
    }
    __shared__ float red[256];
    red[t] = s; __syncthreads();
    for (int st = 128; st > 0; st >>= 1) { if (t < st) red[t] += red[t + st]; __syncthreads(); }
    if (t == 0) inv[m] = rsqrtf(fmaxf(red[0], 1e-12f));
}
// masked row sums of expG (gram epilogue already applied exp)
__global__ void rowsum_k(const float* __restrict__ mask)
{
    const int row = blockIdx.x, t = threadIdx.x;  // 512 threads
    const int b = row >> 9;
    float v = g_G[(size_t)row * L_ + t] * mask[b * L_ + t];
    __shared__ float red[512];
    red[t] = v; __syncthreads();
    for (int st = 256; st > 0; st >>= 1) { if (t < st) red[t] += red[t + st]; __syncthreads(); }
    if (t == 0) g_rowsum[row] = red[0];
}
__global__ void colsum_k(const float* __restrict__ src, const float* __restrict__ wmask,
                         float* __restrict__ dst)
{
    const int b = blockIdx.x, c = blockIdx.y * 128 + threadIdx.x;
    const float* S = src + (size_t)b * L_ * L_;
    float acc = 0.f;
#pragma unroll 4
    for (int r = 0; r < L_; r++) {
        float w = wmask ? wmask[b * L_ + r] : 1.f;
        acc = fmaf(S[(size_t)r * L_ + c], w, acc);
    }
    dst[b * L_ + c] = acc;
}
__global__ void colsum_hk(const __half* __restrict__ src, float* __restrict__ dst)
{
    const int b = blockIdx.x, c = blockIdx.y * 128 + threadIdx.x;
    const __half* S = src + (size_t)b * L_ * L_;
    float acc = 0.f;
#pragma unroll 4
    for (int r = 0; r < L_; r++)
        acc += __half2float(S[(size_t)r * L_ + c]);
    dst[b * L_ + c] = acc;
}
__global__ void qprop_k(const __half* __restrict__ cconvh)
{
    const int b = blockIdx.x, e = blockIdx.y * 128 + threadIdx.x;
    float acc = 0.f;
#pragma unroll 4
    for (int r = 0; r < L_; r++)
        acc = fmaf(g_colsumP[b * L_ + r],
                   __half2float(cconvh[((size_t)(b * L_ + r)) * E_ + e]), acc);
    g_q[b * E_ + e] = acc * g_msum[b];
}
__global__ void a12_k(const float* __restrict__ mask)
{
    __shared__ float s[32][33];
    const int b = blockIdx.z;
    const int i0 = blockIdx.y * 32, j0 = blockIdx.x * 32;
    const int tx = threadIdx.x, ty = threadIdx.y;
    const float* Eb = g_G + (size_t)b * L_ * L_;
    const float* mk = mask + b * L_;
    s[ty][tx] = Eb[(size_t)(i0 + ty) * L_ + j0 + tx];
    __syncthreads();
    float a1 = s[ty][tx] * mk[j0 + tx] / (g_rowsum[b * L_ + i0 + ty] + EPSF) * mk[i0 + ty];
    g_A1h[(size_t)b * L_ * L_ + (size_t)(i0 + ty) * L_ + j0 + tx] = __float2half_rn(a1);
    float a2 = s[tx][ty] * mk[i0 + tx] / (g_colsum[b * L_ + j0 + ty] + EPSF) * mk[j0 + ty];
    g_A2h[(size_t)b * L_ * L_ + (size_t)(j0 + ty) * L_ + i0 + tx] = __float2half_rn(a2);
}
__global__ void pred3_k(const float* __restrict__ X, int D,
                        const float* __restrict__ Wd, const float* __restrict__ bd,
                        float* __restrict__ out, float* __restrict__ conf)
{
    const int m = blockIdx.x, t = threadIdx.x;
    const float* xr = X + (size_t)m * D;
    float a0 = 0.f, a1 = 0.f, a2 = 0.f;
    for (int k4 = t; k4 < D / 4; k4 += 128) {
        float4 x = *reinterpret_cast<const float4*>(xr + k4 * 4);
        float4 w0 = *reinterpret_cast<const float4*>(Wd + k4 * 12);
        float4 w1 = *reinterpret_cast<const float4*>(Wd + k4 * 12 + 4);
        float4 w2 = *reinterpret_cast<const float4*>(Wd + k4 * 12 + 8);
        a0 = fmaf(x.x, w0.x, a0); a1 = fmaf(x.x, w0.y, a1); a2 = fmaf(x.x, w0.z, a2);
        a0 = fmaf(x.y, w0.w, a0); a1 = fmaf(x.y, w1.x, a1); a2 = fmaf(x.y, w1.y, a2);
        a0 = fmaf(x.z, w1.z, a0); a1 = fmaf(x.z, w1.w, a1); a2 = fmaf(x.z, w2.x, a2);
        a0 = fmaf(x.w, w2.y, a0); a1 = fmaf(x.w, w2.z, a1); a2 = fmaf(x.w, w2.w, a2);
    }
#pragma unroll
    for (int o = 16; o > 0; o >>= 1) {
        a0 += __shfl_down_sync(0xffffffffu, a0, o);
        a1 += __shfl_down_sync(0xffffffffu, a1, o);
        a2 += __shfl_down_sync(0xffffffffu, a2, o);
    }
    __shared__ float sh[4][3];
    const int w = t >> 5, ln = t & 31;
    if (ln == 0) { sh[w][0] = a0; sh[w][1] = a1; sh[w][2] = a2; }
    __syncthreads();
    if (t == 0) {
        float p0 = sh[0][0] + sh[1][0] + sh[2][0] + sh[3][0] + bd[0];
        float p1 = sh[0][1] + sh[1][1] + sh[2][1] + sh[3][1] + bd[1];
        float p2 = sh[0][2] + sh[1][2] + sh[2][2] + sh[3][2] + bd[2];
        out[(size_t)m * 3 + 0] = p0;
        out[(size_t)m * 3 + 1] = p1;
        out[(size_t)m * 3 + 2] = p2;
        if (conf) {
            float mx = fmaxf(p0, fmaxf(p1, p2));
            float e0 = expf(p0 - mx), e1 = expf(p1 - mx), e2 = expf(p2 - mx);
            conf[m] = fmaxf(0.f, 1.f - 2.f * e0 / (e0 + e1 + e2));
        }
    }
}
__global__ void msum_k(const float* __restrict__ mask)
{
    const int b = blockIdx.x, t = threadIdx.x;
    __shared__ float red[512];
    red[t] = mask[b * L_ + t]; __syncthreads();
    for (int st = 256; st > 0; st >>= 1) { if (t < st) red[t] += red[t + st]; __syncthreads(); }
    if (t == 0) g_msum[b] = red[0];
}
__global__ void smax_combine_k(const float* __restrict__ mask)
{
    const int row = blockIdx.x, t = threadIdx.x;
    const int b = row >> 9, i = row & 511;
    const size_t base = (size_t)row * L_;
    float v = g_WA[base + t];
    __shared__ float red[512];
    red[t] = v; __syncthreads();
    for (int st = 256; st > 0; st >>= 1) { if (t < st) red[t] = fmaxf(red[t], red[t + st]); __syncthreads(); }
    const float mx = red[0]; __syncthreads();
    float e = expf(v - mx) * mask[b * L_ + t];
    red[t] = e; __syncthreads();
    for (int st = 256; st > 0; st >>= 1) { if (t < st) red[t] += red[t + st]; __syncthreads(); }
    const float sum = red[0];
    float att = e / (sum + EPSF) * mask[b * L_ + i];
    g_WAh[base + t] = __float2half_rn(att + __half2float(g_A1h[base + t]));
}

// =====================================================================
extern "C" void kernel_launch(void* const* d_in, const int* in_sizes, int n_in,
                              void* d_out, int out_size)
{
    const float* aspect_in  = (const float*)d_in[0];
    const float* opinion_in = (const float*)d_in[1];
    const float* context_in = (const float*)d_in[2];
    const float* cq   = (const float*)d_in[3];
    const float* mask = (const float*)d_in[4];
    const float* pos  = (const float*)d_in[5];
    const float* Wa = (const float*)d_in[6],  *ba = (const float*)d_in[7];
    const float* Wo = (const float*)d_in[8],  *bo = (const float*)d_in[9];
    const float* Wc = (const float*)d_in[10], *bc = (const float*)d_in[11];
    const float* Wda = (const float*)d_in[12], *bda = (const float*)d_in[13];
    const float* Wdo = (const float*)d_in[14], *bdo = (const float*)d_in[15];
    const float* Wds = (const float*)d_in[16], *bds = (const float*)d_in[17];
    float* out = (float*)d_out;

    __half *ah, *oh, *ch, *cqh, *posh, *Wah, *Woh, *Wch;
    __half *aconvh, *oconvh, *cconvh, *A1h, *A2h, *Gh, *WAh;
    float *G, *WA, *inva, *invo, *invc, *colsum, *colsumP, *conf, *q;
    cudaGetSymbolAddress((void**)&ah,     g_ah);
    cudaGetSymbolAddress((void**)&oh,     g_oh);
    cudaGetSymbolAddress((void**)&ch,     g_ch);
    cudaGetSymbolAddress((void**)&cqh,    g_cqh);
    cudaGetSymbolAddress((void**)&posh,   g_posh);
    cudaGetSymbolAddress((void**)&Wah,    g_Wah);
    cudaGetSymbolAddress((void**)&Woh,    g_Woh);
    cudaGetSymbolAddress((void**)&Wch,    g_Wch);
    cudaGetSymbolAddress((void**)&aconvh, g_aconvh);
    cudaGetSymbolAddress((void**)&oconvh, g_oconvh);
    cudaGetSymbolAddress((void**)&cconvh, g_cconvh);
    cudaGetSymbolAddress((void**)&A1h,    g_A1h);
    cudaGetSymbolAddress((void**)&A2h,    g_A2h);
    cudaGetSymbolAddress((void**)&Gh,     g_Gh);
    cudaGetSymbolAddress((void**)&WAh,    g_WAh);
    cudaGetSymbolAddress((void**)&G,      g_G);
    cudaGetSymbolAddress((void**)&WA,     g_WA);
    cudaGetSymbolAddress((void**)&inva,   g_inva);
    cudaGetSymbolAddress((void**)&invo,   g_invo);
    cudaGetSymbolAddress((void**)&invc,   g_invc);
    cudaGetSymbolAddress((void**)&colsum, g_colsum);
    cudaGetSymbolAddress((void**)&colsumP,g_colsumP);
    cudaGetSymbolAddress((void**)&conf,   g_conf);
    cudaGetSymbolAddress((void**)&q,      g_q);

    cudaFuncSetAttribute(tc_gemm<true, true>,   cudaFuncAttributeMaxDynamicSharedMemorySize, SMEM_DYN);
    cudaFuncSetAttribute(tc_gemm<false, true>,  cudaFuncAttributeMaxDynamicSharedMemorySize, SMEM_DYN);
    cudaFuncSetAttribute(tc_gemm<false, false>, cudaFuncAttributeMaxDynamicSharedMemorySize, SMEM_DYN);

    // streams/events (created once; capture-safe thereafter)
    static cudaStream_t s1 = nullptr, s2 = nullptr;
    static cudaEvent_t ev[10] = {};
    if (!s1) {
        cudaStreamCreateWithFlags(&s1, cudaStreamNonBlocking);
        cudaStreamCreateWithFlags(&s2, cudaStreamNonBlocking);
        for (int i = 0; i < 10; i++) cudaEventCreateWithFlags(&ev[i], cudaEventDisableTiming);
    }
    cudaEvent_t evRoot = ev[0], evF = ev[1], evPos = ev[2], ev1 = ev[3], ev2 = ev[4],
                evA12 = ev[5], evConf = ev[6], evE1 = ev[7];

    // ---- FORK: side streams enter capture via event from stream 0 ----
    cudaEventRecord(evRoot, 0);
    cudaStreamWaitEvent(s1, evRoot, 0);
    cudaStreamWaitEvent(s2, evRoot, 0);

    // ---- head: conversions. default = conv-gating inputs only ----
    const int nIN = M_ * E_ / 4, nPOS = B_ * L_ * L_ / 4;
    cvt_k<<<(nIN + 255) / 256, 256>>>((const float4*)aspect_in,  (uint2*)ah, nIN);
    cvt_k<<<(nIN + 255) / 256, 256>>>((const float4*)opinion_in, (uint2*)oh, nIN);
    cvt_k<<<(nIN + 255) / 256, 256>>>((const float4*)context_in, (uint2*)ch, nIN);
    cudaEventRecord(evF, 0);

    // s1: Wo, pos, cq conversions, then conv_o after evF
    cvt_k<<<(2304 * 512 / 4 + 255) / 256, 256, 0, s1>>>((const float4*)Wo, (uint2*)Woh, 2304 * 512 / 4);
    cvt_k<<<(nPOS + 255) / 256, 256, 0, s1>>>((const float4*)pos, (uint2*)posh, nPOS);
    cudaEventRecord(evPos, s1);
    cvt_k<<<(nIN + 255) / 256, 256, 0, s1>>>((const float4*)cq, (uint2*)cqh, nIN);
    cudaStreamWaitEvent(s1, evF, 0);
    tc_gemm<true, true><<<dim3(128, 4, 1), 256, SMEM_DYN, s1>>>(
        oh, 0, Woh, 0, 512, 2304, out + OFF_OINT, 0, 1024, bo,
        nullptr, nullptr, nullptr, nullptr, nullptr, nullptr, 0, oconvh, 0, 512, 0);
    rowinv_h<<<M_, 256, 0, s1>>>(oconvh, 512, invo);
    cudaEventRecord(ev1, s1);

    // s2: Wc conversion, conv_c after evF
    cvt_k<<<(2304 * 768 / 4 + 255) / 256, 256, 0, s2>>>((const float4*)Wc, (uint2*)Wch, 2304 * 768 / 4);
    cudaStreamWaitEvent(s2, evF, 0);
    tc_gemm<true, true><<<dim3(128, 6, 1), 256, SMEM_DYN, s2>>>(
        ch, 0, Wch, 0, 768, 2304, out + OFF_CCONV, 0, 768, bc,
        nullptr, nullptr, nullptr, nullptr, nullptr, nullptr, 0, cconvh, 0, 768, 0);
    rowinv_h<<<M_, 256, 0, s2>>>(cconvh, 768, invc);
    cudaEventRecord(ev2, s2);

    // default: Wa conversion + conv_a
    cvt_k<<<(2304 * 512 / 4 + 255) / 256, 256>>>((const float4*)Wa, (uint2*)Wah, 2304 * 512 / 4);
    tc_gemm<true, true><<<dim3(128, 4, 1), 256, SMEM_DYN>>>(
        ah, 0, Wah, 0, 512, 2304, out + OFF_AINT, 0, 1024, ba,
        nullptr, nullptr, nullptr, nullptr, nullptr, nullptr, 0, aconvh, 0, 512, 0);
    rowinv_h<<<M_, 256>>>(aconvh, 512, inva);

    // ---- chain A (default): gram with fused exp (needs oconv -> wait ev1) ----
    cudaStreamWaitEvent(0, ev1, 0);
    tc_gemm<false, false><<<dim3(4, 4, B_), 256, SMEM_DYN>>>(
        aconvh, 512LL * 512, oconvh, 512LL * 512, 512, 512, G, 512LL * 512, 512,
        nullptr, inva, invo, nullptr, nullptr, nullptr, nullptr, 0, nullptr, 0, 0, 1);
    rowsum_k<<<M_, 512>>>(mask);
    colsum_k<<<dim3(B_, 4), 128>>>(G, mask, colsum);
    a12_k<<<dim3(16, 16, B_), dim3(32, 32)>>>(mask);
    cudaEventRecord(evA12, 0);
    tc_gemm<false, true><<<dim3(4, 4, B_), 256, SMEM_DYN>>>(
        A1h, 512LL * 512, oconvh, 512LL * 512, 512, 512, out + OFF_AINT + 512, 512LL * 1024, 1024,
        nullptr, nullptr, nullptr, nullptr, nullptr, nullptr, nullptr, 0, nullptr, 0, 0, 0);
    pred3_k<<<M_, 128>>>(out + OFF_AINT, 1024, Wda, bda, out + OFF_APRED, nullptr);

    // ---- chain B (s1): context-attention front (needs cconv -> wait ev2) ----
    cudaStreamWaitEvent(s1, ev2, 0);
    tc_gemm<false, false><<<dim3(4, 4, B_), 256, SMEM_DYN, s1>>>(
        cqh, 512LL * 768, cconvh, 512LL * 768, 768, 768, nullptr, 0, 512,
        nullptr, nullptr, invc, nullptr, nullptr, nullptr, nullptr, 0, Gh, 512LL * 512, 512, 0);
    tc_gemm<false, true><<<dim3(4, 4, B_), 256, SMEM_DYN, s1>>>(
        Gh, 512LL * 512, posh, 512LL * 512, 512, 512, WA, 512LL * 512, 512,
        nullptr, nullptr, nullptr, nullptr, nullptr, nullptr, nullptr, 0, nullptr, 0, 0, 0);
    cudaStreamWaitEvent(s1, evA12, 0);
    smax_combine_k<<<M_, 512, 0, s1>>>(mask);

    // ---- chain C (s2): propagation pieces + opinion interact/pred ----
    cudaStreamWaitEvent(s2, evPos, 0);
    colsum_hk<<<dim3(B_, 4), 128, 0, s2>>>(posh, colsumP);
    msum_k<<<B_, 512, 0, s2>>>(mask);
    qprop_k<<<dim3(B_, 6), 128, 0, s2>>>(cconvh);
    cudaStreamWaitEvent(s2, evA12, 0);
    tc_gemm<false, true><<<dim3(4, 4, B_), 256, SMEM_DYN, s2>>>(
        A2h, 512LL * 512, aconvh, 512LL * 512, 512, 512, out + OFF_OINT + 512, 512LL * 1024, 1024,
        nullptr, nullptr, nullptr, nullptr, nullptr, nullptr, nullptr, 0, nullptr, 0, 0, 0);
    pred3_k<<<M_, 128, 0, s2>>>(out + OFF_OINT, 1024, Wdo, bdo, out + OFF_OPRED, conf);
    cudaEventRecord(evConf, s2);

    // ---- s1 tail: final context GEMM ----
    cudaStreamWaitEvent(s1, evConf, 0);
    tc_gemm<false, true><<<dim3(4, 6, B_), 256, SMEM_DYN, s1>>>(
        WAh, 512LL * 512, cconvh, 512LL * 768, 768, 512, out + OFF_CINT, 512LL * 768, 768,
        nullptr, nullptr, nullptr, cq, conf, q, nullptr, 0, nullptr, 0, 0, 0);
    pred3_k<<<M_, 128, 0, s1>>>(out + OFF_CINT, 768, Wds, bds, out + OFF_SPRED, nullptr);
    cudaEventRecord(evE1, s1);

    // ---- join ----
    cudaStreamWaitEvent(0, evE1, 0);
    cudaStreamWaitEvent(0, evConf, 0);
}

// round 13
// speedup vs baseline: 1.0337x; 1.0183x over previous
#include <cuda_runtime.h>
#include <cuda_fp16.h>
#include <cstdint>
#include <cstddef>

#define B_  32
#define L_  512
#define E_  768
#define F_  512
#define M_  (B_ * L_)
#define EPSF 1e-7f

#define OFF_APRED 0L
#define OFF_OPRED 49152L
#define OFF_SPRED 98304L
#define OFF_AINT  147456L
#define OFF_OINT  16924672L
#define OFF_CINT  33701888L
#define OFF_CCONV 46284800L

// fp16 operand pools
__device__ __half g_ah  [(size_t)M_ * E_];
__device__ __half g_oh  [(size_t)M_ * E_];
__device__ __half g_ch  [(size_t)M_ * E_];
__device__ __half g_cqh [(size_t)M_ * E_];
__device__ __half g_posh[(size_t)B_ * L_ * L_];
__device__ __half g_Wah [2304 * 512];
__device__ __half g_Woh [2304 * 512];
__device__ __half g_Wch [2304 * 768];
__device__ __half g_aconvh[(size_t)M_ * F_];
__device__ __half g_oconvh[(size_t)M_ * F_];
__device__ __half g_cconvh[(size_t)M_ * E_];
__device__ __half g_A1h[(size_t)B_ * L_ * L_];
__device__ __half g_A2h[(size_t)B_ * L_ * L_];
__device__ __half g_Gh [(size_t)B_ * L_ * L_];
__device__ __half g_WAh[(size_t)B_ * L_ * L_];
// fp32 scratch
__device__ float g_G [(size_t)B_ * L_ * L_];   // holds expG after gram
__device__ float g_WA[(size_t)B_ * L_ * L_];
__device__ float g_inva[M_], g_invo[M_], g_invc[M_];
__device__ float g_rowsum[M_], g_colsum[M_], g_colsumP[M_];
__device__ float g_msum[B_];
__device__ float g_conf[M_];
__device__ float g_q[(size_t)B_ * E_];
__device__ float g_P1[(size_t)M_ * 3];

// ---------------- helpers ----------------
__device__ __forceinline__ uint32_t su32(const void* p) {
    uint32_t a;
    asm("{ .reg .u64 t; cvta.to.shared.u64 t, %1; cvt.u32.u64 %0, t; }" : "=r"(a) : "l"(p));
    return a;
}
__device__ __forceinline__ void ldm_x4(uint32_t* r, uint32_t addr) {
    asm volatile("ldmatrix.sync.aligned.m8n8.x4.shared.b16 {%0,%1,%2,%3}, [%4];"
                 : "=r"(r[0]), "=r"(r[1]), "=r"(r[2]), "=r"(r[3]) : "r"(addr));
}
__device__ __forceinline__ void ldm_x4t(uint32_t* r, uint32_t addr) {
    asm volatile("ldmatrix.sync.aligned.m8n8.x4.trans.shared.b16 {%0,%1,%2,%3}, [%4];"
                 : "=r"(r[0]), "=r"(r[1]), "=r"(r[2]), "=r"(r[3]) : "r"(addr));
}
__device__ __forceinline__ void mma_f16(float* c, const uint32_t* a, const uint32_t* b) {
    asm volatile(
        "mma.sync.aligned.m16n8k16.row.col.f32.f16.f16.f32 "
        "{%0,%1,%2,%3}, {%4,%5,%6,%7}, {%8,%9}, {%0,%1,%2,%3};"
        : "+f"(c[0]), "+f"(c[1]), "+f"(c[2]), "+f"(c[3])
        : "r"(a[0]), "r"(a[1]), "r"(a[2]), "r"(a[3]), "r"(b[0]), "r"(b[1]));
}
__device__ __forceinline__ uint32_t pkh(float x, float y) {
    __half2 t = __floats2half2_rn(x, y);
    return *reinterpret_cast<uint32_t*>(&t);
}

// ---------------- fp16 tensor-core GEMM, BK=64, one barrier/chunk ----------------
#define AROWB 144
#define NROWB 272
#define S_B   18432
#define STAGE 36864
#define SMEM_DYN (2 * STAGE)

template<bool GATHER, bool BNN>
__global__ __launch_bounds__(256, 2)
void tc_gemm(const __half* __restrict__ A, long long ab,
             const __half* __restrict__ Bm, long long bb, int ldb, int K,
             float* __restrict__ C, long long cb, int ldc,
             const float* __restrict__ bias,
             const float* __restrict__ rs, const float* __restrict__ cs,
             const float* __restrict__ addp,
             const float* __restrict__ rowv, const float* __restrict__ colv,
             float* __restrict__ C2, int ldc2,
             __half* __restrict__ Ch, long long cbh, int ldch,
             int doexp)
{
    extern __shared__ char smem[];
    const int tid = threadIdx.x;
    const int lane = tid & 31, wid = tid >> 5;
    const int wm = wid & 3, wn = wid >> 2;
    const int m0 = blockIdx.x * 128, n0 = blockIdx.y * 128, bz = blockIdx.z;
    const uint32_t sb0 = su32(smem);

    const __half* Ab = GATHER ? A : (A + (size_t)bz * ab);
    const __half* Bb = Bm + (size_t)bz * bb;

    float c[2][8][4];
#pragma unroll
    for (int i = 0; i < 2; i++)
#pragma unroll
        for (int j = 0; j < 8; j++)
#pragma unroll
            for (int k = 0; k < 4; k++) c[i][j][k] = 0.f;

    const int nch = K / 64;
    uint4 va[4], vb[4];

    auto ldg = [&](int kc) {
        const int k0 = kc * 64;
#pragma unroll
        for (int p = 0; p < 4; p++) {
            const int idx = tid + p * 256, row = idx >> 3, c16 = idx & 7;
            if (GATHER) {
                const int gm = m0 + row, b = gm >> 9, l = gm & 511;
                const int tap = kc / 12, e0 = (kc - tap * 12) * 64;
                const int src = l + tap - 1;
                va[p] = ((unsigned)src < 512u)
                    ? *reinterpret_cast<const uint4*>(A + ((size_t)(b * 512 + src)) * 768 + e0 + c16 * 8)
                    : make_uint4(0u, 0u, 0u, 0u);
            } else {
                va[p] = *reinterpret_cast<const uint4*>(Ab + (size_t)(m0 + row) * K + k0 + c16 * 8);
            }
        }
        if (BNN) {
#pragma unroll
            for (int p = 0; p < 4; p++) {
                const int idx = tid + p * 256, kr = idx >> 4, c16 = idx & 15;
                vb[p] = *reinterpret_cast<const uint4*>(Bb + (size_t)(k0 + kr) * ldb + n0 + c16 * 8);
            }
        } else {
#pragma unroll
            for (int p = 0; p < 4; p++) {
                const int idx = tid + p * 256, row = idx >> 3, c16 = idx & 7;
                vb[p] = *reinterpret_cast<const uint4*>(Bb + (size_t)(n0 + row) * ldb + k0 + c16 * 8);
            }
        }
    };
    auto sts = [&](int s) {
        char* sp = smem + s * STAGE;
#pragma unroll
        for (int p = 0; p < 4; p++) {
            const int idx = tid + p * 256, row = idx >> 3, c16 = idx & 7;
            *reinterpret_cast<uint4*>(sp + row * AROWB + c16 * 16) = va[p];
        }
        if (BNN) {
#pragma unroll
            for (int p = 0; p < 4; p++) {
                const int idx = tid + p * 256, kr = idx >> 4, c16 = idx & 15;
                *reinterpret_cast<uint4*>(sp + S_B + kr * NROWB + c16 * 16) = vb[p];
            }
        } else {
#pragma unroll
            for (int p = 0; p < 4; p++) {
                const int idx = tid + p * 256, row = idx >> 3, c16 = idx & 7;
                *reinterpret_cast<uint4*>(sp + S_B + row * AROWB + c16 * 16) = vb[p];
            }
        }
    };

    const uint32_t a_lrow = (lane & 15), a_lcol = (lane >> 4) * 8;
    const uint32_t nt_lrow = (lane & 7) + ((lane >> 4) << 3), nt_lcol = ((lane >> 3) & 1) * 8;
    const uint32_t nn_krow = (lane & 7) + (((lane >> 3) & 1) << 3), nn_ncol = (lane >> 4) * 8;

    auto compute = [&](int s) {
        const uint32_t base = sb0 + s * STAGE;
#pragma unroll
        for (int ks = 0; ks < 4; ks++) {
            const int kk = ks * 16;
            uint32_t af[2][4];
#pragma unroll
            for (int mf = 0; mf < 2; mf++)
                ldm_x4(af[mf], base + (wm * 32 + mf * 16 + a_lrow) * AROWB + (kk + a_lcol) * 2);
#pragma unroll
            for (int nf2 = 0; nf2 < 4; nf2++) {
                uint32_t bt[4];
                if (BNN)
                    ldm_x4t(bt, base + S_B + (kk + nn_krow) * NROWB + (wn * 64 + nf2 * 16 + nn_ncol) * 2);
                else
                    ldm_x4(bt, base + S_B + (wn * 64 + nf2 * 16 + nt_lrow) * AROWB + (kk + nt_lcol) * 2);
#pragma unroll
                for (int mf = 0; mf < 2; mf++) {
                    mma_f16(c[mf][nf2 * 2 + 0], af[mf], bt);
                    mma_f16(c[mf][nf2 * 2 + 1], af[mf], bt + 2);
                }
            }
        }
    };

    ldg(0);
    sts(0);
    ldg(1);
    __syncthreads();
    for (int i = 0; i < nch; i++) {
        if (i + 1 < nch) sts((i + 1) & 1);
        if (i + 2 < nch) ldg(i + 2);
        compute(i & 1);
        __syncthreads();
    }

    const int tm = lane >> 2, tn = (lane & 3) * 2;
#pragma unroll
    for (int mf = 0; mf < 2; mf++) {
#pragma unroll
        for (int nf = 0; nf < 8; nf++) {
#pragma unroll
            for (int half = 0; half < 2; half++) {
                const int m = m0 + wm * 32 + mf * 16 + tm + half * 8;
                const int nn = n0 + wn * 64 + nf * 8 + tn;
                float v0 = c[mf][nf][half * 2 + 0];
                float v1 = c[mf][nf][half * 2 + 1];
                if (rs) { const float r = rs[bz * 512 + m]; v0 *= r; v1 *= r; }
                if (cs) { v0 *= cs[bz * 512 + nn]; v1 *= cs[bz * 512 + nn + 1]; }
                if (doexp) { v0 = expf(v0); v1 = expf(v1); }
                if (bias) {
                    v0 = fmaxf(v0 + bias[nn], 0.f);
                    v1 = fmaxf(v1 + bias[nn + 1], 0.f);
                }
                if (C) {
                    const size_t rowoff = (size_t)bz * cb + (size_t)m * ldc + nn;
                    if (addp) { v0 += addp[rowoff]; v1 += addp[rowoff + 1]; }
                    if (rowv) {
                        const float rv = rowv[bz * 512 + m];
                        v0 += rv * colv[(size_t)bz * ldc + nn];
                        v1 += rv * colv[(size_t)bz * ldc + nn + 1];
                    }
                    C[rowoff] = v0; C[rowoff + 1] = v1;
                }
                if (C2) {
                    float* c2 = C2 + (size_t)m * ldc2 + nn;
                    c2[0] = v0; c2[1] = v1;
                }
                if (Ch) {
                    *reinterpret_cast<__half2*>(Ch + (size_t)bz * cbh + (size_t)m * ldch + nn) =
                        __floats2half2_rn(v0, v1);
                }
            }
        }
    }
}

// ---------------- fp32 -> fp16 convert ----------------
__global__ void cvt_k(const float4* __restrict__ src, uint2* __restrict__ dst, int n4)
{
    const int i = blockIdx.x * 256 + threadIdx.x;
    if (i < n4) {
        float4 v = src[i];
        dst[i] = make_uint2(pkh(v.x, v.y), pkh(v.z, v.w));
    }
}

// ---------------- elementwise / reductions ----------------
__global__ void rowinv_h(const __half* __restrict__ X, int D, float* __restrict__ inv)
{
    const int m = blockIdx.x, t = threadIdx.x;
    float s = 0.f;
    const __half2* xr = reinterpret_cast<const __half2*>(X + (size_t)m * D);
    for (int k = t; k < D / 2; k += 256) {
        float2 v = __half22float2(xr[k]);
        s = fmaf(v.x, v.x, fmaf(v.y, v.y, s));
    }
    __shared__ float red[256];
    red[t] = s; __syncthreads();
    for (int st = 128; st > 0; st >>= 1) { if (t < st) red[t] += red[t + st]; __syncthreads(); }
    if (t == 0) inv[m] = rsqrtf(fmaxf(red[0], 1e-12f));
}
__global__ void rowsum_k(const float* __restrict__ mask)
{
    const int row = blockIdx.x, t = threadIdx.x;
    const int b = row >> 9;
    float v = g_G[(size_t)row * L_ + t] * mask[b * L_ + t];
    __shared__ float red[512];
    red[t] = v; __syncthreads();
    for (int st = 256; st > 0; st >>= 1) { if (t < st) red[t] += red[t + st]; __syncthreads(); }
    if (t == 0) g_rowsum[row] = red[0];
}
__global__ void colsum_k(const float* __restrict__ src, const float* __restrict__ wmask,
                         float* __restrict__ dst)
{
    const int b = blockIdx.x, c = blockIdx.y * 128 + threadIdx.x;
    const float* S = src + (size_t)b * L_ * L_;
    float acc = 0.f;
#pragma unroll 4
    for (int r = 0; r < L_; r++) {
        float w = wmask ? wmask[b * L_ + r] : 1.f;
        acc = fmaf(S[(size_t)r * L_ + c], w, acc);
    }
    dst[b * L_ + c] = acc;
}
__global__ void colsum_hk(const __half* __restrict__ src, float* __restrict__ dst)
{
    const int b = blockIdx.x, c = blockIdx.y * 128 + threadIdx.x;
    const __half* S = src + (size_t)b * L_ * L_;
    float acc = 0.f;
#pragma unroll 4
    for (int r = 0; r < L_; r++)
        acc += __half2float(S[(size_t)r * L_ + c]);
    dst[b * L_ + c] = acc;
}
__global__ void qprop_k(const __half* __restrict__ cconvh)
{
    const int b = blockIdx.x, e = blockIdx.y * 128 + threadIdx.x;
    float acc = 0.f;
#pragma unroll 4
    for (int r = 0; r < L_; r++)
        acc = fmaf(g_colsumP[b * L_ + r],
                   __half2float(cconvh[((size_t)(b * L_ + r)) * E_ + e]), acc);
    g_q[b * E_ + e] = acc * g_msum[b];
}
__global__ void a12_k(const float* __restrict__ mask)
{
    __shared__ float s[32][33];
    const int b = blockIdx.z;
    const int i0 = blockIdx.y * 32, j0 = blockIdx.x * 32;
    const int tx = threadIdx.x, ty = threadIdx.y;
    const float* Eb = g_G + (size_t)b * L_ * L_;
    const float* mk = mask + b * L_;
    s[ty][tx] = Eb[(size_t)(i0 + ty) * L_ + j0 + tx];
    __syncthreads();
    float a1 = s[ty][tx] * mk[j0 + tx] / (g_rowsum[b * L_ + i0 + ty] + EPSF) * mk[i0 + ty];
    g_A1h[(size_t)b * L_ * L_ + (size_t)(i0 + ty) * L_ + j0 + tx] = __float2half_rn(a1);
    float a2 = s[tx][ty] * mk[i0 + tx] / (g_colsum[b * L_ + j0 + ty] + EPSF) * mk[j0 + ty];
    g_A2h[(size_t)b * L_ * L_ + (size_t)(j0 + ty) * L_ + i0 + tx] = __float2half_rn(a2);
}
// generic block reduce of 3 accumulators (128 threads)
__device__ __forceinline__ void red3(float& a0, float& a1, float& a2, int t)
{
#pragma unroll
    for (int o = 16; o > 0; o >>= 1) {
        a0 += __shfl_down_sync(0xffffffffu, a0, o);
        a1 += __shfl_down_sync(0xffffffffu, a1, o);
        a2 += __shfl_down_sync(0xffffffffu, a2, o);
    }
    __shared__ float sh[4][3];
    const int w = t >> 5, ln = t & 31;
    if (ln == 0) { sh[w][0] = a0; sh[w][1] = a1; sh[w][2] = a2; }
    __syncthreads();
    if (t == 0) {
        a0 = sh[0][0] + sh[1][0] + sh[2][0] + sh[3][0];
        a1 = sh[0][1] + sh[1][1] + sh[2][1] + sh[3][1];
        a2 = sh[0][2] + sh[1][2] + sh[2][2] + sh[3][2];
    }
}
__global__ void pred3_k(const float* __restrict__ X, int D,
                        const float* __restrict__ Wd, const float* __restrict__ bd,
                        float* __restrict__ out)
{
    const int m = blockIdx.x, t = threadIdx.x;
    const float* xr = X + (size_t)m * D;
    float a0 = 0.f, a1 = 0.f, a2 = 0.f;
    for (int k4 = t; k4 < D / 4; k4 += 128) {
        float4 x = *reinterpret_cast<const float4*>(xr + k4 * 4);
        float4 w0 = *reinterpret_cast<const float4*>(Wd + k4 * 12);
        float4 w1 = *reinterpret_cast<const float4*>(Wd + k4 * 12 + 4);
        float4 w2 = *reinterpret_cast<const float4*>(Wd + k4 * 12 + 8);
        a0 = fmaf(x.x, w0.x, a0); a1 = fmaf(x.x, w0.y, a1); a2 = fmaf(x.x, w0.z, a2);
        a0 = fmaf(x.y, w0.w, a0); a1 = fmaf(x.y, w1.x, a1); a2 = fmaf(x.y, w1.y, a2);
        a0 = fmaf(x.z, w1.z, a0); a1 = fmaf(x.z, w1.w, a1); a2 = fmaf(x.z, w2.x, a2);
        a0 = fmaf(x.w, w2.y, a0); a1 = fmaf(x.w, w2.z, a1); a2 = fmaf(x.w, w2.w, a2);
    }
    red3(a0, a1, a2, t);
    if (t == 0) {
        out[(size_t)m * 3 + 0] = a0 + bd[0];
        out[(size_t)m * 3 + 1] = a1 + bd[1];
        out[(size_t)m * 3 + 2] = a2 + bd[2];
    }
}
// P1[m, :] = aconvh[m, :] @ Wdo[512:1024, :]
__global__ void P1_k(const __half* __restrict__ aconvh, const float* __restrict__ Wd)
{
    const int m = blockIdx.x, t = threadIdx.x;   // 128 threads
    const __half2* xr = reinterpret_cast<const __half2*>(aconvh + (size_t)m * 512);
    float a0 = 0.f, a1 = 0.f, a2 = 0.f;
    for (int k2 = t; k2 < 256; k2 += 128) {
        float2 x = __half22float2(xr[k2]);
        const float* w = Wd + (size_t)(512 + k2 * 2) * 3;
        a0 = fmaf(x.x, w[0], a0); a1 = fmaf(x.x, w[1], a1); a2 = fmaf(x.x, w[2], a2);
        a0 = fmaf(x.y, w[3], a0); a1 = fmaf(x.y, w[4], a1); a2 = fmaf(x.y, w[5], a2);
    }
    red3(a0, a1, a2, t);
    if (t == 0) {
        g_P1[(size_t)m * 3 + 0] = a0;
        g_P1[(size_t)m * 3 + 1] = a1;
        g_P1[(size_t)m * 3 + 2] = a2;
    }
}
// opinion_pred[m] = oconv@Wdo[:512] + A2[m,:]@P1 + bdo ; conf = relu(1-2*softmax0)
__global__ void opred_k(const __half* __restrict__ oconvh, const __half* __restrict__ A2h,
                        const float* __restrict__ Wd, const float* __restrict__ bd,
                        float* __restrict__ out, float* __restrict__ conf)
{
    const int m = blockIdx.x, t = threadIdx.x;   // 128 threads
    const int b = m >> 9;
    float a0 = 0.f, a1 = 0.f, a2 = 0.f;
    const __half2* xr = reinterpret_cast<const __half2*>(oconvh + (size_t)m * 512);
    for (int k2 = t; k2 < 256; k2 += 128) {
        float2 x = __half22float2(xr[k2]);
        const float* w = Wd + (size_t)(k2 * 2) * 3;
        a0 = fmaf(x.x, w[0], a0); a1 = fmaf(x.x, w[1], a1); a2 = fmaf(x.x, w[2], a2);
        a0 = fmaf(x.y, w[3], a0); a1 = fmaf(x.y, w[4], a1); a2 = fmaf(x.y, w[5], a2);
    }
    const __half2* ar = reinterpret_cast<const __half2*>(A2h + (size_t)m * 512);
    const float* P = g_P1 + (size_t)b * 512 * 3;
    for (int k2 = t; k2 < 256; k2 += 128) {
        float2 x = __half22float2(ar[k2]);
        const float* p = P + (size_t)(k2 * 2) * 3;
        a0 = fmaf(x.x, p[0], a0); a1 = fmaf(x.x, p[1], a1); a2 = fmaf(x.x, p[2], a2);
        a0 = fmaf(x.y, p[3], a0); a1 = fmaf(x.y, p[4], a1); a2 = fmaf(x.y, p[5], a2);
    }
    red3(a0, a1, a2, t);
    if (t == 0) {
        float p0 = a0 + bd[0], p1 = a1 + bd[1], p2 = a2 + bd[2];
        out[(size_t)m * 3 + 0] = p0;
        out[(size_t)m * 3 + 1] = p1;
        out[(size_t)m * 3 + 2] = p2;
        float mx = fmaxf(p0, fmaxf(p1, p2));
        float e0 = expf(p0 - mx), e1 = expf(p1 - mx), e2 = expf(p2 - mx);
        conf[m] = fmaxf(0.f, 1.f - 2.f * e0 / (e0 + e1 + e2));
    }
}
__global__ void msum_k(const float* __restrict__ mask)
{
    const int b = blockIdx.x, t = threadIdx.x;
    __shared__ float red[512];
    red[t] = mask[b * L_ + t]; __syncthreads();
    for (int st = 256; st > 0; st >>= 1) { if (t < st) red[t] += red[t + st]; __syncthreads(); }
    if (t == 0) g_msum[b] = red[0];
}
__global__ void smax_combine_k(const float* __restrict__ mask)
{
    const int row = blockIdx.x, t = threadIdx.x;
    const int b = row >> 9, i = row & 511;
    const size_t base = (size_t)row * L_;
    float v = g_WA[base + t];
    __shared__ float red[512];
    red[t] = v; __syncthreads();
    for (int st = 256; st > 0; st >>= 1) { if (t < st) red[t] = fmaxf(red[t], red[t + st]); __syncthreads(); }
    const float mx = red[0]; __syncthreads();
    float e = expf(v - mx) * mask[b * L_ + t];
    red[t] = e; __syncthreads();
    for (int st = 256; st > 0; st >>= 1) { if (t < st) red[t] += red[t + st]; __syncthreads(); }
    const float sum = red[0];
    float att = e / (sum + EPSF) * mask[b * L_ + i];
    g_WAh[base + t] = __float2half_rn(att + __half2float(g_A1h[base + t]));
}

// =====================================================================
extern "C" void kernel_launch(void* const* d_in, const int* in_sizes, int n_in,
                              void* d_out, int out_size)
{
    const float* aspect_in  = (const float*)d_in[0];
    const float* opinion_in = (const float*)d_in[1];
    const float* context_in = (const float*)d_in[2];
    const float* cq   = (const float*)d_in[3];
    const float* mask = (const float*)d_in[4];
    const float* pos  = (const float*)d_in[5];
    const float* Wa = (const float*)d_in[6],  *ba = (const float*)d_in[7];
    const float* Wo = (const float*)d_in[8],  *bo = (const float*)d_in[9];
    const float* Wc = (const float*)d_in[10], *bc = (const float*)d_in[11];
    const float* Wda = (const float*)d_in[12], *bda = (const float*)d_in[13];
    const float* Wdo = (const float*)d_in[14], *bdo = (const float*)d_in[15];
    const float* Wds = (const float*)d_in[16], *bds = (const float*)d_in[17];
    float* out = (float*)d_out;

    __half *ah, *oh, *ch, *cqh, *posh, *Wah, *Woh, *Wch;
    __half *aconvh, *oconvh, *cconvh, *A1h, *A2h, *Gh, *WAh;
    float *G, *WA, *inva, *invo, *invc, *colsum, *colsumP, *conf, *q;
    cudaGetSymbolAddress((void**)&ah,     g_ah);
    cudaGetSymbolAddress((void**)&oh,     g_oh);
    cudaGetSymbolAddress((void**)&ch,     g_ch);
    cudaGetSymbolAddress((void**)&cqh,    g_cqh);
    cudaGetSymbolAddress((void**)&posh,   g_posh);
    cudaGetSymbolAddress((void**)&Wah,    g_Wah);
    cudaGetSymbolAddress((void**)&Woh,    g_Woh);
    cudaGetSymbolAddress((void**)&Wch,    g_Wch);
    cudaGetSymbolAddress((void**)&aconvh, g_aconvh);
    cudaGetSymbolAddress((void**)&oconvh, g_oconvh);
    cudaGetSymbolAddress((void**)&cconvh, g_cconvh);
    cudaGetSymbolAddress((void**)&A1h,    g_A1h);
    cudaGetSymbolAddress((void**)&A2h,    g_A2h);
    cudaGetSymbolAddress((void**)&Gh,     g_Gh);
    cudaGetSymbolAddress((void**)&WAh,    g_WAh);
    cudaGetSymbolAddress((void**)&G,      g_G);
    cudaGetSymbolAddress((void**)&WA,     g_WA);
    cudaGetSymbolAddress((void**)&inva,   g_inva);
    cudaGetSymbolAddress((void**)&invo,   g_invo);
    cudaGetSymbolAddress((void**)&invc,   g_invc);
    cudaGetSymbolAddress((void**)&colsum, g_colsum);
    cudaGetSymbolAddress((void**)&colsumP,g_colsumP);
    cudaGetSymbolAddress((void**)&conf,   g_conf);
    cudaGetSymbolAddress((void**)&q,      g_q);

    cudaFuncSetAttribute(tc_gemm<true, true>,   cudaFuncAttributeMaxDynamicSharedMemorySize, SMEM_DYN);
    cudaFuncSetAttribute(tc_gemm<false, true>,  cudaFuncAttributeMaxDynamicSharedMemorySize, SMEM_DYN);
    cudaFuncSetAttribute(tc_gemm<false, false>, cudaFuncAttributeMaxDynamicSharedMemorySize, SMEM_DYN);

    static cudaStream_t s1 = nullptr, s2 = nullptr;
    static cudaEvent_t ev[10] = {};
    if (!s1) {
        cudaStreamCreateWithFlags(&s1, cudaStreamNonBlocking);
        cudaStreamCreateWithFlags(&s2, cudaStreamNonBlocking);
        for (int i = 0; i < 10; i++) cudaEventCreateWithFlags(&ev[i], cudaEventDisableTiming);
    }
    cudaEvent_t evRoot = ev[0], evPos = ev[1], ev1 = ev[2], ev2 = ev[3],
                evA12 = ev[4], evConf = ev[5], evE1 = ev[6], evC2 = ev[7];

    // ---- FORK ----
    cudaEventRecord(evRoot, 0);
    cudaStreamWaitEvent(s1, evRoot, 0);
    cudaStreamWaitEvent(s2, evRoot, 0);

    const int nIN = M_ * E_ / 4, nPOS = B_ * L_ * L_ / 4;

    // default: aspect path only
    cvt_k<<<(nIN + 255) / 256, 256>>>((const float4*)aspect_in, (uint2*)ah, nIN);
    cvt_k<<<(2304 * 512 / 4 + 255) / 256, 256>>>((const float4*)Wa, (uint2*)Wah, 2304 * 512 / 4);
    tc_gemm<true, true><<<dim3(128, 4, 1), 256, SMEM_DYN>>>(
        ah, 0, Wah, 0, 512, 2304, out + OFF_AINT, 0, 1024, ba,
        nullptr, nullptr, nullptr, nullptr, nullptr, nullptr, 0, aconvh, 0, 512, 0);
    rowinv_h<<<M_, 256>>>(aconvh, 512, inva);

    // s1: opinion path, then cq/pos conversions while idle
    cvt_k<<<(2304 * 512 / 4 + 255) / 256, 256, 0, s1>>>((const float4*)Wo, (uint2*)Woh, 2304 * 512 / 4);
    cvt_k<<<(nIN + 255) / 256, 256, 0, s1>>>((const float4*)opinion_in, (uint2*)oh, nIN);
    tc_gemm<true, true><<<dim3(128, 4, 1), 256, SMEM_DYN, s1>>>(
        oh, 0, Woh, 0, 512, 2304, out + OFF_OINT, 0, 1024, bo,
        nullptr, nullptr, nullptr, nullptr, nullptr, nullptr, 0, oconvh, 0, 512, 0);
    rowinv_h<<<M_, 256, 0, s1>>>(oconvh, 512, invo);
    cudaEventRecord(ev1, s1);
    cvt_k<<<(nIN + 255) / 256, 256, 0, s1>>>((const float4*)cq, (uint2*)cqh, nIN);
    cvt_k<<<(nPOS + 255) / 256, 256, 0, s1>>>((const float4*)pos, (uint2*)posh, nPOS);
    cudaEventRecord(evPos, s1);

    // s2: context path
    cvt_k<<<(2304 * 768 / 4 + 255) / 256, 256, 0, s2>>>((const float4*)Wc, (uint2*)Wch, 2304 * 768 / 4);
    cvt_k<<<(nIN + 255) / 256, 256, 0, s2>>>((const float4*)context_in, (uint2*)ch, nIN);
    tc_gemm<true, true><<<dim3(128, 6, 1), 256, SMEM_DYN, s2>>>(
        ch, 0, Wch, 0, 768, 2304, out + OFF_CCONV, 0, 768, bc,
        nullptr, nullptr, nullptr, nullptr, nullptr, nullptr, 0, cconvh, 0, 768, 0);
    rowinv_h<<<M_, 256, 0, s2>>>(cconvh, 768, invc);
    cudaEventRecord(ev2, s2);

    // ---- chain A (default): gram (fused exp) -> softmasks -> A1 interact -> pred_a
    cudaStreamWaitEvent(0, ev1, 0);
    tc_gemm<false, false><<<dim3(4, 4, B_), 256, SMEM_DYN>>>(
        aconvh, 512LL * 512, oconvh, 512LL * 512, 512, 512, G, 512LL * 512, 512,
        nullptr, inva, invo, nullptr, nullptr, nullptr, nullptr, 0, nullptr, 0, 0, 1);
    rowsum_k<<<M_, 512>>>(mask);
    colsum_k<<<dim3(B_, 4), 128>>>(G, mask, colsum);
    a12_k<<<dim3(16, 16, B_), dim3(32, 32)>>>(mask);
    cudaEventRecord(evA12, 0);
    tc_gemm<false, true><<<dim3(4, 4, B_), 256, SMEM_DYN>>>(
        A1h, 512LL * 512, oconvh, 512LL * 512, 512, 512, out + OFF_AINT + 512, 512LL * 1024, 1024,
        nullptr, nullptr, nullptr, nullptr, nullptr, nullptr, nullptr, 0, nullptr, 0, 0, 0);
    pred3_k<<<M_, 128>>>(out + OFF_AINT, 1024, Wda, bda, out + OFF_APRED);

    // ---- chain B (s1): context-attention front
    cudaStreamWaitEvent(s1, ev2, 0);
    tc_gemm<false, false><<<dim3(4, 4, B_), 256, SMEM_DYN, s1>>>(
        cqh, 512LL * 768, cconvh, 512LL * 768, 768, 768, nullptr, 0, 512,
        nullptr, nullptr, invc, nullptr, nullptr, nullptr, nullptr, 0, Gh, 512LL * 512, 512, 0);
    tc_gemm<false, true><<<dim3(4, 4, B_), 256, SMEM_DYN, s1>>>(
        Gh, 512LL * 512, posh, 512LL * 512, 512, 512, WA, 512LL * 512, 512,
        nullptr, nullptr, nullptr, nullptr, nullptr, nullptr, nullptr, 0, nullptr, 0, 0, 0);
    cudaStreamWaitEvent(s1, evA12, 0);
    smax_combine_k<<<M_, 512, 0, s1>>>(mask);

    // ---- chain C (s2): propagation pieces, fast conf path, then A2 interact
    cudaStreamWaitEvent(s2, evPos, 0);
    colsum_hk<<<dim3(B_, 4), 128, 0, s2>>>(posh, colsumP);
    msum_k<<<B_, 512, 0, s2>>>(mask);
    qprop_k<<<dim3(B_, 6), 128, 0, s2>>>(cconvh);
    cudaStreamWaitEvent(s2, evA12, 0);
    P1_k<<<M_, 128, 0, s2>>>(aconvh, Wdo);
    opred_k<<<M_, 128, 0, s2>>>(oconvh, A2h, Wdo, bdo, out + OFF_OPRED, conf);
    cudaEventRecord(evConf, s2);
    tc_gemm<false, true><<<dim3(4, 4, B_), 256, SMEM_DYN, s2>>>(
        A2h, 512LL * 512, aconvh, 512LL * 512, 512, 512, out + OFF_OINT + 512, 512LL * 1024, 1024,
        nullptr, nullptr, nullptr, nullptr, nullptr, nullptr, nullptr, 0, nullptr, 0, 0, 0);
    cudaEventRecord(evC2, s2);

    // ---- s1 tail: final context GEMM + sentiment pred
    cudaStreamWaitEvent(s1, evConf, 0);
    tc_gemm<false, true><<<dim3(4, 6, B_), 256, SMEM_DYN, s1>>>(
        WAh, 512LL * 512, cconvh, 512LL * 768, 768, 512, out + OFF_CINT, 512LL * 768, 768,
        nullptr, nullptr, nullptr, cq, conf, q, nullptr, 0, nullptr, 0, 0, 0);
    pred3_k<<<M_, 128, 0, s1>>>(out + OFF_CINT, 768, Wds, bds, out + OFF_SPRED);
    cudaEventRecord(evE1, s1);

    // ---- join ----
    cudaStreamWaitEvent(0, evE1, 0);
    cudaStreamWaitEvent(0, evC2, 0);
}

// round 14
// speedup vs baseline: 1.0418x; 1.0078x over previous
#include <cuda_runtime.h>
#include <cuda_fp16.h>
#include <cstdint>
#include <cstddef>

#define B_  32
#define L_  512
#define E_  768
#define F_  512
#define M_  (B_ * L_)
#define EPSF 1e-7f

#define OFF_APRED 0L
#define OFF_OPRED 49152L
#define OFF_SPRED 98304L
#define OFF_AINT  147456L
#define OFF_OINT  16924672L
#define OFF_CINT  33701888L
#define OFF_CCONV 46284800L

__device__ __half g_ah  [(size_t)M_ * E_];
__device__ __half g_oh  [(size_t)M_ * E_];
__device__ __half g_ch  [(size_t)M_ * E_];
__device__ __half g_cqh [(size_t)M_ * E_];
__device__ __half g_posh[(size_t)B_ * L_ * L_];
__device__ __half g_Wah [2304 * 512];
__device__ __half g_Woh [2304 * 512];
__device__ __half g_Wch [2304 * 768];
__device__ __half g_aconvh[(size_t)M_ * F_];
__device__ __half g_oconvh[(size_t)M_ * F_];
__device__ __half g_cconvh[(size_t)M_ * E_];
__device__ __half g_A1h[(size_t)B_ * L_ * L_];
__device__ __half g_A2h[(size_t)B_ * L_ * L_];
__device__ __half g_Gh [(size_t)B_ * L_ * L_];
__device__ __half g_WAh[(size_t)B_ * L_ * L_];
__device__ float g_G [(size_t)B_ * L_ * L_];   // first half reused as fp16 expG
__device__ float g_WA[(size_t)B_ * L_ * L_];
__device__ float g_inva[M_], g_invo[M_], g_invc[M_];
__device__ float g_rowsum[M_], g_colsum[M_], g_colsumP[M_];
__device__ float g_msum[B_];
__device__ float g_conf[M_];
__device__ float g_q[(size_t)B_ * E_];
__device__ float g_P1 [(size_t)M_ * 3];
__device__ float g_P1a[(size_t)M_ * 3];
__device__ float g_Ps [(size_t)M_ * 3];
__device__ float g_qs [B_ * 3];

// ---------------- helpers ----------------
__device__ __forceinline__ uint32_t su32(const void* p) {
    uint32_t a;
    asm("{ .reg .u64 t; cvta.to.shared.u64 t, %1; cvt.u32.u64 %0, t; }" : "=r"(a) : "l"(p));
    return a;
}
__device__ __forceinline__ void ldm_x4(uint32_t* r, uint32_t addr) {
    asm volatile("ldmatrix.sync.aligned.m8n8.x4.shared.b16 {%0,%1,%2,%3}, [%4];"
                 : "=r"(r[0]), "=r"(r[1]), "=r"(r[2]), "=r"(r[3]) : "r"(addr));
}
__device__ __forceinline__ void ldm_x4t(uint32_t* r, uint32_t addr) {
    asm volatile("ldmatrix.sync.aligned.m8n8.x4.trans.shared.b16 {%0,%1,%2,%3}, [%4];"
                 : "=r"(r[0]), "=r"(r[1]), "=r"(r[2]), "=r"(r[3]) : "r"(addr));
}
__device__ __forceinline__ void mma_f16(float* c, const uint32_t* a, const uint32_t* b) {
    asm volatile(
        "mma.sync.aligned.m16n8k16.row.col.f32.f16.f16.f32 "
        "{%0,%1,%2,%3}, {%4,%5,%6,%7}, {%8,%9}, {%0,%1,%2,%3};"
        : "+f"(c[0]), "+f"(c[1]), "+f"(c[2]), "+f"(c[3])
        : "r"(a[0]), "r"(a[1]), "r"(a[2]), "r"(a[3]), "r"(b[0]), "r"(b[1]));
}
__device__ __forceinline__ uint32_t pkh(float x, float y) {
    __half2 t = __floats2half2_rn(x, y);
    return *reinterpret_cast<uint32_t*>(&t);
}

// ---------------- fp16 tensor-core GEMM, BK=64, one barrier/chunk ----------------
#define AROWB 144
#define NROWB 272
#define S_B   18432
#define STAGE 36864
#define SMEM_DYN (2 * STAGE)

template<bool GATHER, bool BNN>
__global__ __launch_bounds__(256, 2)
void tc_gemm(const __half* __restrict__ A, long long ab,
             const __half* __restrict__ Bm, long long bb, int ldb, int K,
             float* __restrict__ C, long long cb, int ldc,
             const float* __restrict__ bias,
             const float* __restrict__ rs, const float* __restrict__ cs,
             const float* __restrict__ addp,
             const float* __restrict__ rowv, const float* __restrict__ colv,
             float* __restrict__ C2, int ldc2,
             __half* __restrict__ Ch, long long cbh, int ldch,
             int doexp)
{
    extern __shared__ char smem[];
    const int tid = threadIdx.x;
    const int lane = tid & 31, wid = tid >> 5;
    const int wm = wid & 3, wn = wid >> 2;
    const int m0 = blockIdx.x * 128, n0 = blockIdx.y * 128, bz = blockIdx.z;
    const uint32_t sb0 = su32(smem);

    const __half* Ab = GATHER ? A : (A + (size_t)bz * ab);
    const __half* Bb = Bm + (size_t)bz * bb;

    float c[2][8][4];
#pragma unroll
    for (int i = 0; i < 2; i++)
#pragma unroll
        for (int j = 0; j < 8; j++)
#pragma unroll
            for (int k = 0; k < 4; k++) c[i][j][k] = 0.f;

    const int nch = K / 64;
    uint4 va[4], vb[4];

    auto ldg = [&](int kc) {
        const int k0 = kc * 64;
#pragma unroll
        for (int p = 0; p < 4; p++) {
            const int idx = tid + p * 256, row = idx >> 3, c16 = idx & 7;
            if (GATHER) {
                const int gm = m0 + row, b = gm >> 9, l = gm & 511;
                const int tap = kc / 12, e0 = (kc - tap * 12) * 64;
                const int src = l + tap - 1;
                va[p] = ((unsigned)src < 512u)
                    ? *reinterpret_cast<const uint4*>(A + ((size_t)(b * 512 + src)) * 768 + e0 + c16 * 8)
                    : make_uint4(0u, 0u, 0u, 0u);
            } else {
                va[p] = *reinterpret_cast<const uint4*>(Ab + (size_t)(m0 + row) * K + k0 + c16 * 8);
            }
        }
        if (BNN) {
#pragma unroll
            for (int p = 0; p < 4; p++) {
                const int idx = tid + p * 256, kr = idx >> 4, c16 = idx & 15;
                vb[p] = *reinterpret_cast<const uint4*>(Bb + (size_t)(k0 + kr) * ldb + n0 + c16 * 8);
            }
        } else {
#pragma unroll
            for (int p = 0; p < 4; p++) {
                const int idx = tid + p * 256, row = idx >> 3, c16 = idx & 7;
                vb[p] = *reinterpret_cast<const uint4*>(Bb + (size_t)(n0 + row) * ldb + k0 + c16 * 8);
            }
        }
    };
    auto sts = [&](int s) {
        char* sp = smem + s * STAGE;
#pragma unroll
        for (int p = 0; p < 4; p++) {
            const int idx = tid + p * 256, row = idx >> 3, c16 = idx & 7;
            *reinterpret_cast<uint4*>(sp + row * AROWB + c16 * 16) = va[p];
        }
        if (BNN) {
#pragma unroll
            for (int p = 0; p < 4; p++) {
                const int idx = tid + p * 256, kr = idx >> 4, c16 = idx & 15;
                *reinterpret_cast<uint4*>(sp + S_B + kr * NROWB + c16 * 16) = vb[p];
            }
        } else {
#pragma unroll
            for (int p = 0; p < 4; p++) {
                const int idx = tid + p * 256, row = idx >> 3, c16 = idx & 7;
                *reinterpret_cast<uint4*>(sp + S_B + row * AROWB + c16 * 16) = vb[p];
            }
        }
    };

    const uint32_t a_lrow = (lane & 15), a_lcol = (lane >> 4) * 8;
    const uint32_t nt_lrow = (lane & 7) + ((lane >> 4) << 3), nt_lcol = ((lane >> 3) & 1) * 8;
    const uint32_t nn_krow = (lane & 7) + (((lane >> 3) & 1) << 3), nn_ncol = (lane >> 4) * 8;

    auto compute = [&](int s) {
        const uint32_t base = sb0 + s * STAGE;
#pragma unroll
        for (int ks = 0; ks < 4; ks++) {
            const int kk = ks * 16;
            uint32_t af[2][4];
#pragma unroll
            for (int mf = 0; mf < 2; mf++)
                ldm_x4(af[mf], base + (wm * 32 + mf * 16 + a_lrow) * AROWB + (kk + a_lcol) * 2);
#pragma unroll
            for (int nf2 = 0; nf2 < 4; nf2++) {
                uint32_t bt[4];
                if (BNN)
                    ldm_x4t(bt, base + S_B + (kk + nn_krow) * NROWB + (wn * 64 + nf2 * 16 + nn_ncol) * 2);
                else
                    ldm_x4(bt, base + S_B + (wn * 64 + nf2 * 16 + nt_lrow) * AROWB + (kk + nt_lcol) * 2);
#pragma unroll
                for (int mf = 0; mf < 2; mf++) {
                    mma_f16(c[mf][nf2 * 2 + 0], af[mf], bt);
                    mma_f16(c[mf][nf2 * 2 + 1], af[mf], bt + 2);
                }
            }
        }
    };

    ldg(0);
    sts(0);
    ldg(1);
    __syncthreads();
    for (int i = 0; i < nch; i++) {
        if (i + 1 < nch) sts((i + 1) & 1);
        if (i + 2 < nch) ldg(i + 2);
        compute(i & 1);
        __syncthreads();
    }

    const int tm = lane >> 2, tn = (lane & 3) * 2;
#pragma unroll
    for (int mf = 0; mf < 2; mf++) {
#pragma unroll
        for (int nf = 0; nf < 8; nf++) {
#pragma unroll
            for (int half = 0; half < 2; half++) {
                const int m = m0 + wm * 32 + mf * 16 + tm + half * 8;
                const int nn = n0 + wn * 64 + nf * 8 + tn;
                float v0 = c[mf][nf][half * 2 + 0];
                float v1 = c[mf][nf][half * 2 + 1];
                if (rs) { const float r = rs[bz * 512 + m]; v0 *= r; v1 *= r; }
                if (cs) { v0 *= cs[bz * 512 + nn]; v1 *= cs[bz * 512 + nn + 1]; }
                if (doexp) { v0 = expf(v0); v1 = expf(v1); }
                if (bias) {
                    v0 = fmaxf(v0 + bias[nn], 0.f);
                    v1 = fmaxf(v1 + bias[nn + 1], 0.f);
                }
                if (C) {
                    const size_t rowoff = (size_t)bz * cb + (size_t)m * ldc + nn;
                    if (addp) { v0 += addp[rowoff]; v1 += addp[rowoff + 1]; }
                    if (rowv) {
                        const float rv = rowv[bz * 512 + m];
                        v0 += rv * colv[(size_t)bz * ldc + nn];
                        v1 += rv * colv[(size_t)bz * ldc + nn + 1];
                    }
                    C[rowoff] = v0; C[rowoff + 1] = v1;
                }
                if (C2) {
                    float* c2 = C2 + (size_t)m * ldc2 + nn;
                    c2[0] = v0; c2[1] = v1;
                }
                if (Ch) {
                    *reinterpret_cast<__half2*>(Ch + (size_t)bz * cbh + (size_t)m * ldch + nn) =
                        __floats2half2_rn(v0, v1);
                }
            }
        }
    }
}

// ---------------- fp32 -> fp16 convert ----------------
__global__ void cvt_k(const float4* __restrict__ src, uint2* __restrict__ dst, int n4)
{
    const int i = blockIdx.x * 256 + threadIdx.x;
    if (i < n4) {
        float4 v = src[i];
        dst[i] = make_uint2(pkh(v.x, v.y), pkh(v.z, v.w));
    }
}

// ---------------- elementwise / reductions ----------------
__global__ void rowinv_h(const __half* __restrict__ X, int D, float* __restrict__ inv)
{
    const int m = blockIdx.x, t = threadIdx.x;
    float s = 0.f;
    const __half2* xr = reinterpret_cast<const __half2*>(X + (size_t)m * D);
    for (int k = t; k < D / 2; k += 256) {
        float2 v = __half22float2(xr[k]);
        s = fmaf(v.x, v.x, fmaf(v.y, v.y, s));
    }
    __shared__ float red[256];
    red[t] = s; __syncthreads();
    for (int st = 128; st > 0; st >>= 1) { if (t < st) red[t] += red[t + st]; __syncthreads(); }
    if (t == 0) inv[m] = rsqrtf(fmaxf(red[0], 1e-12f));
}
// masked row sums of fp16 expG (stored in g_G's memory)
__global__ void rowsum_k(const float* __restrict__ mask)
{
    const __half* eG = reinterpret_cast<const __half*>(g_G);
    const int row = blockIdx.x, t = threadIdx.x;
    const int b = row >> 9;
    float v = __half2float(eG[(size_t)row * L_ + t]) * mask[b * L_ + t];
    __shared__ float red[512];
    red[t] = v; __syncthreads();
    for (int st = 256; st > 0; st >>= 1) { if (t < st) red[t] += red[t + st]; __syncthreads(); }
    if (t == 0) g_rowsum[row] = red[0];
}
// column sums of fp16 matrix, optional row weights
__global__ void colsum_hk(const __half* __restrict__ src, const float* __restrict__ wmask,
                          float* __restrict__ dst)
{
    const int b = blockIdx.x, c = blockIdx.y * 128 + threadIdx.x;
    const __half* S = src + (size_t)b * L_ * L_;
    float acc = 0.f;
#pragma unroll 4
    for (int r = 0; r < L_; r++) {
        float w = wmask ? wmask[b * L_ + r] : 1.f;
        acc = fmaf(__half2float(S[(size_t)r * L_ + c]), w, acc);
    }
    dst[b * L_ + c] = acc;
}
__global__ void qprop_k(const __half* __restrict__ cconvh)
{
    const int b = blockIdx.x, e = blockIdx.y * 128 + threadIdx.x;
    float acc = 0.f;
#pragma unroll 4
    for (int r = 0; r < L_; r++)
        acc = fmaf(g_colsumP[b * L_ + r],
                   __half2float(cconvh[((size_t)(b * L_ + r)) * E_ + e]), acc);
    g_q[b * E_ + e] = acc * g_msum[b];
}
__global__ void a12_k(const float* __restrict__ mask)
{
    const __half* eG = reinterpret_cast<const __half*>(g_G);
    __shared__ float s[32][33];
    const int b = blockIdx.z;
    const int i0 = blockIdx.y * 32, j0 = blockIdx.x * 32;
    const int tx = threadIdx.x, ty = threadIdx.y;
    const __half* Eb = eG + (size_t)b * L_ * L_;
    const float* mk = mask + b * L_;
    s[ty][tx] = __half2float(Eb[(size_t)(i0 + ty) * L_ + j0 + tx]);
    __syncthreads();
    float a1 = s[ty][tx] * mk[j0 + tx] / (g_rowsum[b * L_ + i0 + ty] + EPSF) * mk[i0 + ty];
    g_A1h[(size_t)b * L_ * L_ + (size_t)(i0 + ty) * L_ + j0 + tx] = __float2half_rn(a1);
    float a2 = s[tx][ty] * mk[i0 + tx] / (g_colsum[b * L_ + j0 + ty] + EPSF) * mk[j0 + ty];
    g_A2h[(size_t)b * L_ * L_ + (size_t)(j0 + ty) * L_ + i0 + tx] = __float2half_rn(a2);
}
__device__ __forceinline__ void red3(float& a0, float& a1, float& a2, int t)
{
#pragma unroll
    for (int o = 16; o > 0; o >>= 1) {
        a0 += __shfl_down_sync(0xffffffffu, a0, o);
        a1 += __shfl_down_sync(0xffffffffu, a1, o);
        a2 += __shfl_down_sync(0xffffffffu, a2, o);
    }
    __shared__ float sh[4][3];
    const int w = t >> 5, ln = t & 31;
    if (ln == 0) { sh[w][0] = a0; sh[w][1] = a1; sh[w][2] = a2; }
    __syncthreads();
    if (t == 0) {
        a0 = sh[0][0] + sh[1][0] + sh[2][0] + sh[3][0];
        a1 = sh[0][1] + sh[1][1] + sh[2][1] + sh[3][1];
        a2 = sh[0][2] + sh[1][2] + sh[2][2] + sh[3][2];
    }
}
// out[m,:] = Xh[m,:D] @ Wd[:D,:3]
__global__ void pk_k(const __half* __restrict__ Xh, int D,
                     const float* __restrict__ Wd, float* __restrict__ out)
{
    const int m = blockIdx.x, t = threadIdx.x;
    const __half2* xr = reinterpret_cast<const __half2*>(Xh + (size_t)m * D);
    float a0 = 0.f, a1 = 0.f, a2 = 0.f;
    for (int k2 = t; k2 < D / 2; k2 += 128) {
        float2 x = __half22float2(xr[k2]);
        const float* w = Wd + (size_t)(k2 * 2) * 3;
        a0 = fmaf(x.x, w[0], a0); a1 = fmaf(x.x, w[1], a1); a2 = fmaf(x.x, w[2], a2);
        a0 = fmaf(x.y, w[3], a0); a1 = fmaf(x.y, w[4], a1); a2 = fmaf(x.y, w[5], a2);
    }
    red3(a0, a1, a2, t);
    if (t == 0) {
        out[(size_t)m * 3 + 0] = a0;
        out[(size_t)m * 3 + 1] = a1;
        out[(size_t)m * 3 + 2] = a2;
    }
}
// pred[m] = Xh[m,:512]@Wd[:512] + Ah[m,:]·P[b rows] + bd ; optional conf
__global__ void xpred_k(const __half* __restrict__ Xh, const __half* __restrict__ Ah,
                        const float* __restrict__ Wd, const float* __restrict__ P,
                        const float* __restrict__ bd,
                        float* __restrict__ out, float* __restrict__ conf)
{
    const int m = blockIdx.x, t = threadIdx.x;
    const int b = m >> 9;
    float a0 = 0.f, a1 = 0.f, a2 = 0.f;
    const __half2* xr = reinterpret_cast<const __half2*>(Xh + (size_t)m * 512);
    for (int k2 = t; k2 < 256; k2 += 128) {
        float2 x = __half22float2(xr[k2]);
        const float* w = Wd + (size_t)(k2 * 2) * 3;
        a0 = fmaf(x.x, w[0], a0); a1 = fmaf(x.x, w[1], a1); a2 = fmaf(x.x, w[2], a2);
        a0 = fmaf(x.y, w[3], a0); a1 = fmaf(x.y, w[4], a1); a2 = fmaf(x.y, w[5], a2);
    }
    const __half2* ar = reinterpret_cast<const __half2*>(Ah + (size_t)m * 512);
    const float* Pb = P + (size_t)b * 512 * 3;
    for (int k2 = t; k2 < 256; k2 += 128) {
        float2 x = __half22float2(ar[k2]);
        const float* p = Pb + (size_t)(k2 * 2) * 3;
        a0 = fmaf(x.x, p[0], a0); a1 = fmaf(x.x, p[1], a1); a2 = fmaf(x.x, p[2], a2);
        a0 = fmaf(x.y, p[3], a0); a1 = fmaf(x.y, p[4], a1); a2 = fmaf(x.y, p[5], a2);
    }
    red3(a0, a1, a2, t);
    if (t == 0) {
        float p0 = a0 + bd[0], p1 = a1 + bd[1], p2 = a2 + bd[2];
        out[(size_t)m * 3 + 0] = p0;
        out[(size_t)m * 3 + 1] = p1;
        out[(size_t)m * 3 + 2] = p2;
        if (conf) {
            float mx = fmaxf(p0, fmaxf(p1, p2));
            float e0 = expf(p0 - mx), e1 = expf(p1 - mx), e2 = expf(p2 - mx);
            conf[m] = fmaxf(0.f, 1.f - 2.f * e0 / (e0 + e1 + e2));
        }
    }
}
// qs[b,:] = q[b,:768]@Wds
__global__ void qs_k(const float* __restrict__ Wd)
{
    const int b = blockIdx.x, t = threadIdx.x;
    float a0 = 0.f, a1 = 0.f, a2 = 0.f;
    for (int k = t; k < 768; k += 128) {
        float x = g_q[b * 768 + k];
        const float* w = Wd + (size_t)k * 3;
        a0 = fmaf(x, w[0], a0); a1 = fmaf(x, w[1], a1); a2 = fmaf(x, w[2], a2);
    }
    red3(a0, a1, a2, t);
    if (t == 0) { g_qs[b * 3] = a0; g_qs[b * 3 + 1] = a1; g_qs[b * 3 + 2] = a2; }
}
// sentiment_pred[m] = cq[m]@Wds + WAh[m,:]·Ps[b rows] + conf[m]*qs[b] + bds
__global__ void spred_k(const float* __restrict__ cq, const float* __restrict__ Wd,
                        const float* __restrict__ bd, float* __restrict__ out)
{
    const int m = blockIdx.x, t = threadIdx.x;
    const int b = m >> 9;
    float a0 = 0.f, a1 = 0.f, a2 = 0.f;
    const float* xr = cq + (size_t)m * 768;
    for (int k = t; k < 768; k += 128) {
        float x = xr[k];
        const float* w = Wd + (size_t)k * 3;
        a0 = fmaf(x, w[0], a0); a1 = fmaf(x, w[1], a1); a2 = fmaf(x, w[2], a2);
    }
    const __half2* ar = reinterpret_cast<const __half2*>(g_WAh + (size_t)m * 512);
    const float* Pb = g_Ps + (size_t)b * 512 * 3;
    for (int k2 = t; k2 < 256; k2 += 128) {
        float2 x = __half22float2(ar[k2]);
        const float* p = Pb + (size_t)(k2 * 2) * 3;
        a0 = fmaf(x.x, p[0], a0); a1 = fmaf(x.x, p[1], a1); a2 = fmaf(x.x, p[2], a2);
        a0 = fmaf(x.y, p[3], a0); a1 = fmaf(x.y, p[4], a1); a2 = fmaf(x.y, p[5], a2);
    }
    red3(a0, a1, a2, t);
    if (t == 0) {
        const float cf = g_conf[m];
        out[(size_t)m * 3 + 0] = a0 + bd[0] + cf * g_qs[b * 3 + 0];
        out[(size_t)m * 3 + 1] = a1 + bd[1] + cf * g_qs[b * 3 + 1];
        out[(size_t)m * 3 + 2] = a2 + bd[2] + cf * g_qs[b * 3 + 2];
    }
}
__global__ void msum_k(const float* __restrict__ mask)
{
    const int b = blockIdx.x, t = threadIdx.x;
    __shared__ float red[512];
    red[t] = mask[b * L_ + t]; __syncthreads();
    for (int st = 256; st > 0; st >>= 1) { if (t < st) red[t] += red[t + st]; __syncthreads(); }
    if (t == 0) g_msum[b] = red[0];
}
__global__ void smax_combine_k(const float* __restrict__ mask)
{
    const int row = blockIdx.x, t = threadIdx.x;
    const int b = row >> 9, i = row & 511;
    const size_t base = (size_t)row * L_;
    float v = g_WA[base + t];
    __shared__ float red[512];
    red[t] = v; __syncthreads();
    for (int st = 256; st > 0; st >>= 1) { if (t < st) red[t] = fmaxf(red[t], red[t + st]); __syncthreads(); }
    const float mx = red[0]; __syncthreads();
    float e = expf(v - mx) * mask[b * L_ + t];
    red[t] = e; __syncthreads();
    for (int st = 256; st > 0; st >>= 1) { if (t < st) red[t] += red[t + st]; __syncthreads(); }
    const float sum = red[0];
    float att = e / (sum + EPSF) * mask[b * L_ + i];
    g_WAh[base + t] = __float2half_rn(att + __half2float(g_A1h[base + t]));
}

// =====================================================================
extern "C" void kernel_launch(void* const* d_in, const int* in_sizes, int n_in,
                              void* d_out, int out_size)
{
    const float* aspect_in  = (const float*)d_in[0];
    const float* opinion_in = (const float*)d_in[1];
    const float* context_in = (const float*)d_in[2];
    const float* cq   = (const float*)d_in[3];
    const float* mask = (const float*)d_in[4];
    const float* pos  = (const float*)d_in[5];
    const float* Wa = (const float*)d_in[6],  *ba = (const float*)d_in[7];
    const float* Wo = (const float*)d_in[8],  *bo = (const float*)d_in[9];
    const float* Wc = (const float*)d_in[10], *bc = (const float*)d_in[11];
    const float* Wda = (const float*)d_in[12], *bda = (const float*)d_in[13];
    const float* Wdo = (const float*)d_in[14], *bdo = (const float*)d_in[15];
    const float* Wds = (const float*)d_in[16], *bds = (const float*)d_in[17];
    float* out = (float*)d_out;

    __half *ah, *oh, *ch, *cqh, *posh, *Wah, *Woh, *Wch;
    __half *aconvh, *oconvh, *cconvh, *A1h, *A2h, *Gh, *WAh;
    float *G, *WA, *inva, *invo, *invc, *colsum, *colsumP, *conf, *q;
    float *P1, *P1a, *Ps;
    cudaGetSymbolAddress((void**)&ah,     g_ah);
    cudaGetSymbolAddress((void**)&oh,     g_oh);
    cudaGetSymbolAddress((void**)&ch,     g_ch);
    cudaGetSymbolAddress((void**)&cqh,    g_cqh);
    cudaGetSymbolAddress((void**)&posh,   g_posh);
    cudaGetSymbolAddress((void**)&Wah,    g_Wah);
    cudaGetSymbolAddress((void**)&Woh,    g_Woh);
    cudaGetSymbolAddress((void**)&Wch,    g_Wch);
    cudaGetSymbolAddress((void**)&aconvh, g_aconvh);
    cudaGetSymbolAddress((void**)&oconvh, g_oconvh);
    cudaGetSymbolAddress((void**)&cconvh, g_cconvh);
    cudaGetSymbolAddress((void**)&A1h,    g_A1h);
    cudaGetSymbolAddress((void**)&A2h,    g_A2h);
    cudaGetSymbolAddress((void**)&Gh,     g_Gh);
    cudaGetSymbolAddress((void**)&WAh,    g_WAh);
    cudaGetSymbolAddress((void**)&G,      g_G);
    cudaGetSymbolAddress((void**)&WA,     g_WA);
    cudaGetSymbolAddress((void**)&inva,   g_inva);
    cudaGetSymbolAddress((void**)&invo,   g_invo);
    cudaGetSymbolAddress((void**)&invc,   g_invc);
    cudaGetSymbolAddress((void**)&colsum, g_colsum);
    cudaGetSymbolAddress((void**)&colsumP,g_colsumP);
    cudaGetSymbolAddress((void**)&conf,   g_conf);
    cudaGetSymbolAddress((void**)&q,      g_q);
    cudaGetSymbolAddress((void**)&P1,     g_P1);
    cudaGetSymbolAddress((void**)&P1a,    g_P1a);
    cudaGetSymbolAddress((void**)&Ps,     g_Ps);
    __half* eGh = reinterpret_cast<__half*>(G);   // fp16 expG in g_G storage

    cudaFuncSetAttribute(tc_gemm<true, true>,   cudaFuncAttributeMaxDynamicSharedMemorySize, SMEM_DYN);
    cudaFuncSetAttribute(tc_gemm<false, true>,  cudaFuncAttributeMaxDynamicSharedMemorySize, SMEM_DYN);
    cudaFuncSetAttribute(tc_gemm<false, false>, cudaFuncAttributeMaxDynamicSharedMemorySize, SMEM_DYN);

    static cudaStream_t s1 = nullptr, s2 = nullptr;
    static cudaEvent_t ev[12] = {};
    if (!s1) {
        cudaStreamCreateWithFlags(&s1, cudaStreamNonBlocking);
        cudaStreamCreateWithFlags(&s2, cudaStreamNonBlocking);
        for (int i = 0; i < 12; i++) cudaEventCreateWithFlags(&ev[i], cudaEventDisableTiming);
    }
    cudaEvent_t evRoot = ev[0], evPos = ev[1], ev1 = ev[2], ev2 = ev[3],
                evA12 = ev[4], evConf = ev[5], evE1 = ev[6], evC2 = ev[7],
                evP1a = ev[8], evSmax = ev[9];

    // ---- FORK ----
    cudaEventRecord(evRoot, 0);
    cudaStreamWaitEvent(s1, evRoot, 0);
    cudaStreamWaitEvent(s2, evRoot, 0);

    const int nIN = M_ * E_ / 4, nPOS = B_ * L_ * L_ / 4;

    // default: aspect path
    cvt_k<<<(nIN + 255) / 256, 256>>>((const float4*)aspect_in, (uint2*)ah, nIN);
    cvt_k<<<(2304 * 512 / 4 + 255) / 256, 256>>>((const float4*)Wa, (uint2*)Wah, 2304 * 512 / 4);
    tc_gemm<true, true><<<dim3(128, 4, 1), 256, SMEM_DYN>>>(
        ah, 0, Wah, 0, 512, 2304, out + OFF_AINT, 0, 1024, ba,
        nullptr, nullptr, nullptr, nullptr, nullptr, nullptr, 0, aconvh, 0, 512, 0);
    rowinv_h<<<M_, 256>>>(aconvh, 512, inva);

    // s1: opinion path, then P1a + cq/pos conversions
    cvt_k<<<(2304 * 512 / 4 + 255) / 256, 256, 0, s1>>>((const float4*)Wo, (uint2*)Woh, 2304 * 512 / 4);
    cvt_k<<<(nIN + 255) / 256, 256, 0, s1>>>((const float4*)opinion_in, (uint2*)oh, nIN);
    tc_gemm<true, true><<<dim3(128, 4, 1), 256, SMEM_DYN, s1>>>(
        oh, 0, Woh, 0, 512, 2304, out + OFF_OINT, 0, 1024, bo,
        nullptr, nullptr, nullptr, nullptr, nullptr, nullptr, 0, oconvh, 0, 512, 0);
    rowinv_h<<<M_, 256, 0, s1>>>(oconvh, 512, invo);
    cudaEventRecord(ev1, s1);
    pk_k<<<M_, 128, 0, s1>>>(oconvh, 512, Wda + 512 * 3, P1a);   // P1a = oconv@Wda[512:]
    cudaEventRecord(evP1a, s1);
    cvt_k<<<(nIN + 255) / 256, 256, 0, s1>>>((const float4*)cq, (uint2*)cqh, nIN);
    cvt_k<<<(nPOS + 255) / 256, 256, 0, s1>>>((const float4*)pos, (uint2*)posh, nPOS);
    cudaEventRecord(evPos, s1);

    // s2: context path + Ps
    cvt_k<<<(2304 * 768 / 4 + 255) / 256, 256, 0, s2>>>((const float4*)Wc, (uint2*)Wch, 2304 * 768 / 4);
    cvt_k<<<(nIN + 255) / 256, 256, 0, s2>>>((const float4*)context_in, (uint2*)ch, nIN);
    tc_gemm<true, true><<<dim3(128, 6, 1), 256, SMEM_DYN, s2>>>(
        ch, 0, Wch, 0, 768, 2304, out + OFF_CCONV, 0, 768, bc,
        nullptr, nullptr, nullptr, nullptr, nullptr, nullptr, 0, cconvh, 0, 768, 0);
    rowinv_h<<<M_, 256, 0, s2>>>(cconvh, 768, invc);
    cudaEventRecord(ev2, s2);
    pk_k<<<M_, 128, 0, s2>>>(cconvh, 768, Wds, Ps);              // Ps = cconv@Wds

    // ---- chain A (default): gram -> fp16 expG -> softmasks -> apred -> A1 GEMM
    cudaStreamWaitEvent(0, ev1, 0);
    tc_gemm<false, false><<<dim3(4, 4, B_), 256, SMEM_DYN>>>(
        aconvh, 512LL * 512, oconvh, 512LL * 512, 512, 512, nullptr, 0, 512,
        nullptr, inva, invo, nullptr, nullptr, nullptr, nullptr, 0, eGh, 512LL * 512, 512, 1);
    rowsum_k<<<M_, 512>>>(mask);
    colsum_hk<<<dim3(B_, 4), 128>>>(eGh, mask, colsum);
    a12_k<<<dim3(16, 16, B_), dim3(32, 32)>>>(mask);
    cudaEventRecord(evA12, 0);
    cudaStreamWaitEvent(0, evP1a, 0);
    xpred_k<<<M_, 128>>>(aconvh, A1h, Wda, P1a, bda, out + OFF_APRED, nullptr);
    tc_gemm<false, true><<<dim3(4, 4, B_), 256, SMEM_DYN>>>(
        A1h, 512LL * 512, oconvh, 512LL * 512, 512, 512, out + OFF_AINT + 512, 512LL * 1024, 1024,
        nullptr, nullptr, nullptr, nullptr, nullptr, nullptr, nullptr, 0, nullptr, 0, 0, 0);

    // ---- chain B (s1): context-attention front
    cudaStreamWaitEvent(s1, ev2, 0);
    tc_gemm<false, false><<<dim3(4, 4, B_), 256, SMEM_DYN, s1>>>(
        cqh, 512LL * 768, cconvh, 512LL * 768, 768, 768, nullptr, 0, 512,
        nullptr, nullptr, invc, nullptr, nullptr, nullptr, nullptr, 0, Gh, 512LL * 512, 512, 0);
    tc_gemm<false, true><<<dim3(4, 4, B_), 256, SMEM_DYN, s1>>>(
        Gh, 512LL * 512, posh, 512LL * 512, 512, 512, WA, 512LL * 512, 512,
        nullptr, nullptr, nullptr, nullptr, nullptr, nullptr, nullptr, 0, nullptr, 0, 0, 0);
    cudaStreamWaitEvent(s1, evA12, 0);
    smax_combine_k<<<M_, 512, 0, s1>>>(mask);
    cudaEventRecord(evSmax, s1);

    // ---- chain C (s2): propagation pieces, fast conf, spred, A2 GEMM
    cudaStreamWaitEvent(s2, evPos, 0);
    colsum_hk<<<dim3(B_, 4), 128, 0, s2>>>(posh, nullptr, colsumP);
    msum_k<<<B_, 512, 0, s2>>>(mask);
    qprop_k<<<dim3(B_, 6), 128, 0, s2>>>(cconvh);
    qs_k<<<B_, 128, 0, s2>>>(Wds);
    cudaStreamWaitEvent(s2, evA12, 0);
    pk_k<<<M_, 128, 0, s2>>>(aconvh, 512, Wdo + 512 * 3, P1);    // P1 = aconv@Wdo[512:]
    xpred_k<<<M_, 128, 0, s2>>>(oconvh, A2h, Wdo, P1, bdo, out + OFF_OPRED, conf);
    cudaEventRecord(evConf, s2);
    cudaStreamWaitEvent(s2, evSmax, 0);
    spred_k<<<M_, 128, 0, s2>>>(cq, Wds, bds, out + OFF_SPRED);
    tc_gemm<false, true><<<dim3(4, 4, B_), 256, SMEM_DYN, s2>>>(
        A2h, 512LL * 512, aconvh, 512LL * 512, 512, 512, out + OFF_OINT + 512, 512LL * 1024, 1024,
        nullptr, nullptr, nullptr, nullptr, nullptr, nullptr, nullptr, 0, nullptr, 0, 0, 0);
    cudaEventRecord(evC2, s2);

    // ---- s1 tail: final context GEMM (writes CINT output)
    cudaStreamWaitEvent(s1, evConf, 0);
    tc_gemm<false, true><<<dim3(4, 6, B_), 256, SMEM_DYN, s1>>>(
        WAh, 512LL * 512, cconvh, 512LL * 768, 768, 512, out + OFF_CINT, 512LL * 768, 768,
        nullptr, nullptr, nullptr, cq, conf, q, nullptr, 0, nullptr, 0, 0, 0);
    cudaEventRecord(evE1, s1);

    // ---- join ----
    cudaStreamWaitEvent(0, evE1, 0);
    cudaStreamWaitEvent(0, evC2, 0);
}